// round 5
// baseline (speedup 1.0000x reference)
#include <cuda_runtime.h>
#include <cuda_bf16.h>
#include <math.h>

// Problem constants
#define BB    8
#define CC    256
#define NN    4096          // 16*16*16
#define MM    512           // HIDDEN == M
#define EE    16
#define NH    8
#define HD    64
#define JJ    1024          // 2*HIDDEN
#define FFNH  2048
#define EPSV  1.1920929e-07f

// ---------------- scratch (__device__ globals; no allocation allowed) ----------------
__device__ float g_PE  [NN * MM];            // 8 MB   pos_enc [N,512]
__device__ float g_RINV[BB * NN];            // 128 KB rmsnorm inverse per (b,n)
__device__ float g_K   [(size_t)BB * NN * MM]; // 64 MB
__device__ float g_V   [(size_t)BB * NN * MM]; // 64 MB
__device__ float g_Q   [BB * EE * MM];       // 256 KB
__device__ float g_MOLN[BB * EE * MM];       // 256 KB normalized mol (residual)
__device__ float g_S   [(size_t)BB * NH * EE * NN]; // 33.5 MB scores/probs
__device__ float g_AOP [8 * BB * EE * MM];   // 2 MB  AV partials (8 n-chunks) - deterministic
__device__ float g_ATT [BB * EE * MM];       // 256 KB attended

__device__ __forceinline__ float geluf(float x) {
    return 0.5f * x * (1.0f + erff(x * 0.70710678118654752440f));
}

// block reduction, NWARPS warps participate fully
template <int NWARPS, bool DOMAX>
__device__ __forceinline__ float blk_red(float v, float* red) {
    #pragma unroll
    for (int o = 16; o; o >>= 1) {
        float t = __shfl_xor_sync(0xffffffffu, v, o);
        v = DOMAX ? fmaxf(v, t) : v + t;
    }
    if ((threadIdx.x & 31) == 0) red[threadIdx.x >> 5] = v;
    __syncthreads();
    if (threadIdx.x < 32) {
        float r = (threadIdx.x < NWARPS) ? red[threadIdx.x] : (DOMAX ? -1e30f : 0.0f);
        #pragma unroll
        for (int o = NWARPS >> 1; o; o >>= 1) {
            float t = __shfl_xor_sync(0xffffffffu, r, o);
            r = DOMAX ? fmaxf(r, t) : r + t;
        }
        if (threadIdx.x == 0) red[0] = r;
    }
    __syncthreads();
    float s = red[0];
    __syncthreads();
    return s;
}

// ---------------- K1: positional encoding MLP: [4096,3]->gelu->[4096,512] --------------
// 16 spatial positions per block; each thread owns hidden channel c=tid for all 16.
__global__ void k_pos(const float* __restrict__ w1, const float* __restrict__ b1,
                      const float* __restrict__ w2, const float* __restrict__ b2) {
    __shared__ float h1[16][257];
    int n0 = blockIdx.x * 16;
    int t  = threadIdx.x;  // 256
    float w1d = w1[t], w1h = w1[256 + t], w1w = w1[512 + t], bb = b1[t];
    #pragma unroll
    for (int nn = 0; nn < 16; nn++) {
        int n = n0 + nn;
        float cd = (float)(n >> 8)        * 0.0625f;
        float ch = (float)((n >> 4) & 15) * 0.0625f;
        float cw = (float)(n & 15)        * 0.0625f;
        float a = cd * w1d + ch * w1h + cw * w1w + bb;
        h1[nn][t] = geluf(a);
    }
    __syncthreads();
    #pragma unroll
    for (int rep = 0; rep < 2; rep++) {
        int j = t + rep * 256;
        float bj = b2[j];
        float acc[16];
        #pragma unroll
        for (int nn = 0; nn < 16; nn++) acc[nn] = bj;
        for (int k = 0; k < 256; k++) {
            float w = w2[k * 512 + j];
            #pragma unroll
            for (int nn = 0; nn < 16; nn++) acc[nn] += h1[nn][k] * w;
        }
        #pragma unroll
        for (int nn = 0; nn < 16; nn++) g_PE[(n0 + nn) * 512 + j] = acc[nn];
    }
}

// ---------------- K2: patch rmsnorm rsqrt factor per (b,n) -----------------------------
__global__ void k_rinv(const float* __restrict__ X) {
    int t = blockIdx.x * blockDim.x + threadIdx.x;  // B*N threads
    int b = t >> 12, n = t & (NN - 1);
    const float* p = X + (size_t)b * CC * NN + n;
    float s = 0.0f;
    #pragma unroll 8
    for (int c = 0; c < CC; c++) { float v = p[(size_t)c * NN]; s += v * v; }
    g_RINV[t] = rsqrtf(s * (1.0f / 256.0f) + EPSV);
}

// ---------------- K3: KV GEMM (the big one): O[n,j] = rinv*Sum_c X[c,n]*wp[c]*Wkv[c,j] --
// 128(n) x 64(j) tile, 256 threads, 8x4 microtile, K-step 16.
__global__ void __launch_bounds__(256) k_kv(const float* __restrict__ X,
                                            const float* __restrict__ wkv,
                                            const float* __restrict__ bkv,
                                            const float* __restrict__ wp) {
    __shared__ __align__(16) float As[16][128];
    __shared__ __align__(16) float Bs[16][64];
    int b  = blockIdx.z;
    int n0 = blockIdx.x * 128;
    int j0 = blockIdx.y * 64;
    int t  = threadIdx.x;
    int tx = t & 15, ty = t >> 4;
    const float* Xb = X + (size_t)b * CC * NN;
    float acc[8][4];
    #pragma unroll
    for (int i = 0; i < 8; i++)
        #pragma unroll
        for (int u = 0; u < 4; u++) acc[i][u] = 0.0f;

    for (int c0 = 0; c0 < CC; c0 += 16) {
        #pragma unroll
        for (int i = 0; i < 8; i++) {
            int idx = t + i * 256;               // 0..2047
            int kk = idx >> 7, nn = idx & 127;
            As[kk][nn] = Xb[(size_t)(c0 + kk) * NN + n0 + nn];
        }
        #pragma unroll
        for (int i = 0; i < 4; i++) {
            int idx = t + i * 256;               // 0..1023
            int kk = idx >> 6, jj = idx & 63;
            Bs[kk][jj] = wp[c0 + kk] * wkv[(size_t)(c0 + kk) * JJ + j0 + jj];
        }
        __syncthreads();
        #pragma unroll
        for (int kk = 0; kk < 16; kk++) {
            float4 a0 = *(const float4*)&As[kk][ty * 8];
            float4 a1 = *(const float4*)&As[kk][ty * 8 + 4];
            float4 b4 = *(const float4*)&Bs[kk][tx * 4];
            float a[8] = {a0.x, a0.y, a0.z, a0.w, a1.x, a1.y, a1.z, a1.w};
            float bw[4] = {b4.x, b4.y, b4.z, b4.w};
            #pragma unroll
            for (int i = 0; i < 8; i++)
                #pragma unroll
                for (int u = 0; u < 4; u++) acc[i][u] += a[i] * bw[u];
        }
        __syncthreads();
    }
    #pragma unroll
    for (int i = 0; i < 8; i++) {
        int n = n0 + ty * 8 + i;
        float r = g_RINV[b * NN + n];
        const float* pe = &g_PE[n * 512];
        #pragma unroll
        for (int u = 0; u < 4; u++) {
            int j = j0 + tx * 4 + u;
            float val = acc[i][u] * r + bkv[j] + pe[j & 511];
            if (j < 512) g_K[((size_t)b * NN + n) * MM + j]         = val;
            else         g_V[((size_t)b * NN + n) * MM + (j - 512)] = val;
        }
    }
}

// ---------------- K4: mol rmsnorm + Q projection, 4 rows per block ---------------------
__global__ void k_molq(const float* __restrict__ mol, const float* __restrict__ wmol,
                       const float* __restrict__ wq, const float* __restrict__ bq) {
    __shared__ float sm[4][512];
    __shared__ float red[32];
    int row0 = blockIdx.x * 4;
    int t = threadIdx.x;  // 512
    float wm = wmol[t];
    float xr[4];
    #pragma unroll
    for (int r = 0; r < 4; r++) xr[r] = mol[(row0 + r) * 512 + t];
    #pragma unroll
    for (int r = 0; r < 4; r++) {
        float ss = blk_red<16, false>(xr[r] * xr[r], red);
        float xn = xr[r] * rsqrtf(ss * (1.0f / 512.0f) + EPSV) * wm;
        sm[r][t] = xn;
        g_MOLN[(row0 + r) * 512 + t] = xn;
    }
    __syncthreads();
    float bv = bq[t];
    float acc[4] = {bv, bv, bv, bv};
    for (int m = 0; m < 512; m++) {
        float w = wq[m * 512 + t];
        #pragma unroll
        for (int r = 0; r < 4; r++) acc[r] += sm[r][m] * w;
    }
    #pragma unroll
    for (int r = 0; r < 4; r++) g_Q[(row0 + r) * 512 + t] = acc[r];
}

// ---------------- K5: scores[b,h,e,n] = 0.125 * q.k ------------------------------------
__global__ void k_scores() {
    __shared__ float qs[16][64];
    __shared__ float ks[16][65];
    int b = blockIdx.z, h = blockIdx.y, n0 = blockIdx.x * 16;
    int t = threadIdx.x;  // 256
    #pragma unroll
    for (int i = t; i < 1024; i += 256) {
        int r = i >> 6, d = i & 63;
        qs[r][d] = g_Q[(b * 16 + r) * 512 + h * 64 + d];
        ks[r][d] = g_K[((size_t)b * NN + n0 + r) * MM + h * 64 + d];
    }
    __syncthreads();
    int e = t >> 4, nn = t & 15;
    float acc = 0.0f;
    #pragma unroll
    for (int d = 0; d < 64; d++) acc += qs[e][d] * ks[nn][d];
    g_S[(((size_t)b * NH + h) * EE + e) * NN + n0 + nn] = acc * 0.125f;
}

// ---------------- K6: softmax over n=4096, one row per block ---------------------------
__global__ void k_softmax() {
    __shared__ float red[32];
    int row = blockIdx.x;   // b*128 + h*16 + e
    float* s = g_S + (size_t)row * NN;
    int t = threadIdx.x;    // 256
    float loc[16];
    float m = -1e30f;
    #pragma unroll
    for (int i = 0; i < 16; i++) { loc[i] = s[t + i * 256]; m = fmaxf(m, loc[i]); }
    m = blk_red<8, true>(m, red);
    float sum = 0.0f;
    #pragma unroll
    for (int i = 0; i < 16; i++) { loc[i] = expf(loc[i] - m); sum += loc[i]; }
    sum = blk_red<8, false>(sum, red);
    float inv = 1.0f / sum;
    #pragma unroll
    for (int i = 0; i < 16; i++) s[t + i * 256] = loc[i] * inv;
}

// ---------------- K7: out = P @ V, n-chunked partials (deterministic, no atomics) ------
__global__ void k_av() {
    int bh = blockIdx.x;           // 0..63
    int c  = blockIdx.y;           // 0..7 n-chunk
    int b = bh >> 3, h = bh & 7;
    int t = threadIdx.x;           // 256
    int d  = t & 63;
    int e0 = (t >> 6) * 4;
    int n0 = c * 512;
    const float* V = g_V + ((size_t)b * NN + n0) * MM + h * 64 + d;
    const float* S = g_S + ((size_t)bh * EE + e0) * NN + n0;
    float acc[4] = {0.f, 0.f, 0.f, 0.f};
    #pragma unroll 4
    for (int n = 0; n < 512; n++) {
        float v = V[(size_t)n * MM];
        #pragma unroll
        for (int i = 0; i < 4; i++) acc[i] += S[(size_t)i * NN + n] * v;
    }
    #pragma unroll
    for (int i = 0; i < 4; i++)
        g_AOP[(size_t)c * (BB * EE * MM) + (b * 16 + e0 + i) * 512 + h * 64 + d] = acc[i];
}

// ---------------- K8: chunk-reduce + proj + residual, 4 rows/block ---------------------
__global__ void k_proj(const float* __restrict__ wproj, const float* __restrict__ bproj) {
    __shared__ float sm[4][512];
    int row0 = blockIdx.x * 4;
    int t = threadIdx.x;  // 512
    #pragma unroll
    for (int r = 0; r < 4; r++) {
        float v = 0.0f;
        #pragma unroll
        for (int c = 0; c < 8; c++) v += g_AOP[(size_t)c * (BB * EE * MM) + (row0 + r) * 512 + t];
        sm[r][t] = v;
    }
    __syncthreads();
    float bp = bproj[t];
    float acc[4] = {bp, bp, bp, bp};
    for (int j = 0; j < 512; j++) {
        float w = wproj[j * 512 + t];
        #pragma unroll
        for (int r = 0; r < 4; r++) acc[r] += sm[r][j] * w;
    }
    #pragma unroll
    for (int r = 0; r < 4; r++)
        g_ATT[(row0 + r) * 512 + t] = acc[r] + g_MOLN[(row0 + r) * 512 + t];
}

// ---------------- K9: FFN (rmsnorm -> 512x2048 gelu -> 2048x512 + residual) ------------
__global__ void k_ffn(const float* __restrict__ nw,
                      const float* __restrict__ w1, const float* __restrict__ b1,
                      const float* __restrict__ w2, const float* __restrict__ b2,
                      float* __restrict__ out) {
    __shared__ float s[4][512];
    __shared__ float h1[4][2048];
    __shared__ float red[32];
    int row0 = blockIdx.x * 4;
    int t = threadIdx.x;  // 512
    float nwt = nw[t];
    float xr[4];
    #pragma unroll
    for (int r = 0; r < 4; r++) xr[r] = g_ATT[(row0 + r) * 512 + t];
    #pragma unroll
    for (int r = 0; r < 4; r++) {
        float ss = blk_red<16, false>(xr[r] * xr[r], red);
        s[r][t] = xr[r] * rsqrtf(ss * (1.0f / 512.0f) + EPSV) * nwt;
    }
    __syncthreads();
    #pragma unroll
    for (int rep = 0; rep < 4; rep++) {
        int j = t + rep * 512;
        float bb = b1[j];
        float acc[4] = {bb, bb, bb, bb};
        for (int m = 0; m < 512; m++) {
            float w = w1[m * FFNH + j];
            #pragma unroll
            for (int r = 0; r < 4; r++) acc[r] += s[r][m] * w;
        }
        #pragma unroll
        for (int r = 0; r < 4; r++) h1[r][j] = geluf(acc[r]);
    }
    __syncthreads();
    float bb = b2[t];
    float acc[4] = {bb, bb, bb, bb};
    for (int k = 0; k < FFNH; k++) {
        float w = w2[k * 512 + t];
        #pragma unroll
        for (int r = 0; r < 4; r++) acc[r] += h1[r][k] * w;
    }
    #pragma unroll
    for (int r = 0; r < 4; r++) out[(row0 + r) * 512 + t] = acc[r] + xr[r];
}

// ---------------- launch --------------------------------------------------------------
extern "C" void kernel_launch(void* const* d_in, const int* in_sizes, int n_in,
                              void* d_out, int out_size) {
    const float* patch   = (const float*)d_in[0];
    const float* mol     = (const float*)d_in[1];
    const float* pe_w1   = (const float*)d_in[2];
    const float* pe_b1   = (const float*)d_in[3];
    const float* pe_w2   = (const float*)d_in[4];
    const float* pe_b2   = (const float*)d_in[5];
    const float* wq      = (const float*)d_in[6];
    const float* bq      = (const float*)d_in[7];
    const float* wkv     = (const float*)d_in[8];
    const float* bkv     = (const float*)d_in[9];
    const float* wproj   = (const float*)d_in[10];
    const float* bproj   = (const float*)d_in[11];
    const float* nmolw   = (const float*)d_in[12];
    const float* npatchw = (const float*)d_in[13];
    const float* ffn_w1  = (const float*)d_in[14];
    const float* ffn_b1  = (const float*)d_in[15];
    const float* ffn_w2  = (const float*)d_in[16];
    const float* ffn_b2  = (const float*)d_in[17];
    const float* ffn_nw  = (const float*)d_in[18];
    float* out = (float*)d_out;

    (void)in_sizes; (void)n_in; (void)out_size;

    k_pos    <<<NN / 16, 256>>>(pe_w1, pe_b1, pe_w2, pe_b2);
    k_rinv   <<<(BB * NN) / 256, 256>>>(patch);
    k_kv     <<<dim3(NN / 128, JJ / 64, BB), 256>>>(patch, wkv, bkv, npatchw);
    k_molq   <<<(BB * EE) / 4, 512>>>(mol, nmolw, wq, bq);
    k_scores <<<dim3(NN / 16, NH, BB), 256>>>();
    k_softmax<<<BB * NH * EE, 256>>>();
    k_av     <<<dim3(BB * NH, 8), 256>>>();
    k_proj   <<<(BB * EE) / 4, 512>>>(wproj, bproj);
    k_ffn    <<<(BB * EE) / 4, 512>>>(ffn_nw, ffn_w1, ffn_b1, ffn_w2, ffn_b2, out);
}

// round 6
// speedup vs baseline: 2.2808x; 2.2808x over previous
#include <cuda_runtime.h>
#include <math.h>

#define BB 8
#define CC 256
#define NN 4096
#define MM 512
#define EE 16
#define NH 8
#define FFNH 2048
#define EPSV 1.1920929e-07f

// ------------- scratch (__device__ globals; no allocation allowed) ---------------
__device__ float g_PE  [NN * MM];             // pos_enc [n][512]          8 MB
__device__ float g_PET [MM * NN];             // pos_enc transposed [j][n] 8 MB
__device__ float g_RINV[BB * NN];             // patch rmsnorm rsqrt
__device__ float g_Q   [128 * 512];           // q rows=(b,e)
__device__ float g_MOLN[128 * 512];           // normalized mol (residual)
__device__ float g_TQ  [BB * 128 * 256];      // tq' rows=(b, h*16+e), wp folded
__device__ float g_QBK [BB * NH * EE];        // q . bk  (per b,h,e)
__device__ float g_S   [(size_t)BB * 128 * NN];   // scores/probs  16.8 MB
__device__ float g_PAP [(size_t)16 * BB * 128 * 256]; // pa partials (16 ksplit) 16.8 MB
__device__ float g_OPEP[4 * 64 * 16 * 64];    // p@pe partials (4 ksplit)
__device__ float g_ATT0[128 * 512];           // attention out (pre-proj)
__device__ float g_ATT [128 * 512];           // attended (post residual)
__device__ float g_ATTN[128 * 512];           // ffn-normed
__device__ float g_H1  [128 * 2048];          // ffn hidden

__device__ __forceinline__ float geluf(float x) {
    return 0.5f * x * (1.0f + erff(x * 0.70710678118654752440f));
}

template <int NWARPS, bool DOMAX>
__device__ __forceinline__ float blk_red(float v, float* red) {
    #pragma unroll
    for (int o = 16; o; o >>= 1) {
        float t = __shfl_xor_sync(0xffffffffu, v, o);
        v = DOMAX ? fmaxf(v, t) : v + t;
    }
    if ((threadIdx.x & 31) == 0) red[threadIdx.x >> 5] = v;
    __syncthreads();
    if (threadIdx.x < 32) {
        float r = (threadIdx.x < NWARPS) ? red[threadIdx.x] : (DOMAX ? -1e30f : 0.0f);
        #pragma unroll
        for (int o = NWARPS >> 1; o; o >>= 1) {
            float t = __shfl_xor_sync(0xffffffffu, r, o);
            r = DOMAX ? fmaxf(r, t) : r + t;
        }
        if (threadIdx.x == 0) red[0] = r;
    }
    __syncthreads();
    float s = red[0];
    __syncthreads();
    return s;
}

// ---------------- K1: positional encoding MLP, writes PE and PET -----------------
__global__ void k_pos(const float* __restrict__ w1, const float* __restrict__ b1,
                      const float* __restrict__ w2, const float* __restrict__ b2) {
    __shared__ float h1[16][257];
    int n0 = blockIdx.x * 16;
    int t  = threadIdx.x;  // 256
    float w1d = w1[t], w1h = w1[256 + t], w1w = w1[512 + t], bb = b1[t];
    #pragma unroll
    for (int nn = 0; nn < 16; nn++) {
        int n = n0 + nn;
        float cd = (float)(n >> 8)        * 0.0625f;
        float ch = (float)((n >> 4) & 15) * 0.0625f;
        float cw = (float)(n & 15)        * 0.0625f;
        h1[nn][t] = geluf(cd * w1d + ch * w1h + cw * w1w + bb);
    }
    __syncthreads();
    #pragma unroll
    for (int rep = 0; rep < 2; rep++) {
        int j = t + rep * 256;
        float bj = b2[j];
        float acc[16];
        #pragma unroll
        for (int nn = 0; nn < 16; nn++) acc[nn] = bj;
        for (int k = 0; k < 256; k++) {
            float w = w2[k * 512 + j];
            #pragma unroll
            for (int nn = 0; nn < 16; nn++) acc[nn] += h1[nn][k] * w;
        }
        #pragma unroll
        for (int nn = 0; nn < 16; nn++) {
            g_PE [(size_t)(n0 + nn) * 512 + j]  = acc[nn];
            g_PET[(size_t)j * 4096 + n0 + nn]   = acc[nn];
        }
    }
}

// ---------------- K2: patch rmsnorm rsqrt factor ---------------------------------
__global__ void k_rinv(const float* __restrict__ X) {
    int t = blockIdx.x * blockDim.x + threadIdx.x;
    int b = t >> 12, n = t & (NN - 1);
    const float* p = X + (size_t)b * CC * NN + n;
    float s = 0.0f;
    #pragma unroll 8
    for (int c = 0; c < CC; c++) { float v = p[(size_t)c * NN]; s += v * v; }
    g_RINV[t] = rsqrtf(s * (1.0f / 256.0f) + EPSV);
}

// ---------------- K3: mol rmsnorm + Q projection (K-split small GEMM) -------------
// grid(16 rowgrp, 4 colgrp), 256 thr, 8 rows, 128 cols, K=512 split over 8 warps
__global__ void __launch_bounds__(256) k_molq(const float* __restrict__ mol,
                                              const float* __restrict__ wmol,
                                              const float* __restrict__ wq,
                                              const float* __restrict__ bq) {
    __shared__ float x_s[8][512];
    __shared__ float part[8][8][128];
    int row0 = blockIdx.x * 8, jb = blockIdx.y * 128;
    int t = threadIdx.x;
    int w = t >> 5, lane = t & 31;
    // warp w normalizes row w
    float vals[16]; float ss = 0.0f;
    #pragma unroll
    for (int i = 0; i < 16; i++) {
        float v = mol[(row0 + w) * 512 + lane + i * 32];
        vals[i] = v; ss += v * v;
    }
    #pragma unroll
    for (int o = 16; o; o >>= 1) ss += __shfl_xor_sync(0xffffffffu, ss, o);
    float rv = rsqrtf(ss * (1.0f / 512.0f) + EPSV);
    #pragma unroll
    for (int i = 0; i < 16; i++) {
        int m = lane + i * 32;
        float xn = vals[i] * rv * wmol[m];
        x_s[w][m] = xn;
        if (blockIdx.y == 0) g_MOLN[(row0 + w) * 512 + m] = xn;
    }
    __syncthreads();
    int tk = w, tj = lane, j = jb + tj * 4;
    float4 acc[8];
    #pragma unroll
    for (int r = 0; r < 8; r++) acc[r] = make_float4(0.f, 0.f, 0.f, 0.f);
    #pragma unroll 4
    for (int c = tk * 64; c < tk * 64 + 64; c++) {
        float4 w4 = *(const float4*)&wq[(size_t)c * 512 + j];
        #pragma unroll
        for (int r = 0; r < 8; r++) {
            float x = x_s[r][c];
            acc[r].x += x * w4.x; acc[r].y += x * w4.y;
            acc[r].z += x * w4.z; acc[r].w += x * w4.w;
        }
    }
    #pragma unroll
    for (int r = 0; r < 8; r++) *(float4*)&part[tk][r][tj * 4] = acc[r];
    __syncthreads();
    {
        int r = t >> 5, cq = t & 31, j2 = jb + cq * 4;
        float4 s = make_float4(0.f, 0.f, 0.f, 0.f);
        #pragma unroll
        for (int k2 = 0; k2 < 8; k2++) {
            float4 p = *(const float4*)&part[k2][r][cq * 4];
            s.x += p.x; s.y += p.y; s.z += p.z; s.w += p.w;
        }
        float4 bv = *(const float4*)&bq[j2];
        s.x += bv.x; s.y += bv.y; s.z += bv.z; s.w += bv.w;
        *(float4*)&g_Q[(row0 + r) * 512 + j2] = s;
    }
}

// ---------------- K4: tq'[b,h,e,c] = wp[c] * sum_d q . Wk[c, h*64+d]; also q.bk ----
__global__ void __launch_bounds__(256) k_tq(const float* __restrict__ wkv,
                                            const float* __restrict__ bkv,
                                            const float* __restrict__ wp) {
    __shared__ float qs[16][64];
    __shared__ float wk_s[64][65];
    int b = blockIdx.x, h = blockIdx.y, t = threadIdx.x;
    {
        int e = t >> 4, d0 = (t & 15) * 4;
        *(float4*)&qs[e][d0] = *(const float4*)&g_Q[(b * 16 + e) * 512 + h * 64 + d0];
    }
    __syncthreads();
    if (t < 16) {
        float s = 0.f;
        #pragma unroll
        for (int d = 0; d < 64; d++) s += qs[t][d] * bkv[h * 64 + d];
        g_QBK[(b * 8 + h) * 16 + t] = s;
    }
    for (int c0 = 0; c0 < 256; c0 += 64) {
        {
            int cl = t >> 2, d0 = (t & 3) * 16;
            #pragma unroll
            for (int q4 = 0; q4 < 4; q4++) {
                float4 v = *(const float4*)&wkv[(size_t)(c0 + cl) * 1024 + h * 64 + d0 + q4 * 4];
                wk_s[d0 + q4 * 4 + 0][cl] = v.x;
                wk_s[d0 + q4 * 4 + 1][cl] = v.y;
                wk_s[d0 + q4 * 4 + 2][cl] = v.z;
                wk_s[d0 + q4 * 4 + 3][cl] = v.w;
            }
        }
        __syncthreads();
        int e = t >> 4, c4 = (t & 15) * 4;
        float acc[4] = {0.f, 0.f, 0.f, 0.f};
        #pragma unroll
        for (int d = 0; d < 64; d++) {
            float qv = qs[e][d];
            acc[0] += qv * wk_s[d][c4 + 0];
            acc[1] += qv * wk_s[d][c4 + 1];
            acc[2] += qv * wk_s[d][c4 + 2];
            acc[3] += qv * wk_s[d][c4 + 3];
        }
        int c = c0 + c4;
        float4 wpv = *(const float4*)&wp[c];
        float4 o = make_float4(acc[0] * wpv.x, acc[1] * wpv.y, acc[2] * wpv.z, acc[3] * wpv.w);
        *(float4*)&g_TQ[((size_t)b * 128 + h * 16 + (t >> 4)) * 256 + c] = o;
        __syncthreads();
    }
}

// ---------------- K5: qpe: g_S = q @ PET(h-slice) + qbk  (per h) ------------------
// grid(32 ntile, 8 h), 256 thr, M=128(be) x N=128(n) x K=64
__global__ void __launch_bounds__(256) k_qpe() {
    __shared__ float As[16][128];
    __shared__ float Bs[16][128];
    int n0 = blockIdx.x * 128, h = blockIdx.y, t = threadIdx.x;
    int tr = t >> 4, tc = t & 15;
    float acc[8][8];
    #pragma unroll
    for (int i = 0; i < 8; i++)
        #pragma unroll
        for (int j = 0; j < 8; j++) acc[i][j] = 0.f;
    for (int k0 = 0; k0 < 64; k0 += 16) {
        {
            int r = t >> 1, k8 = (t & 1) * 8;
            float4 a0 = *(const float4*)&g_Q[r * 512 + h * 64 + k0 + k8];
            float4 a1 = *(const float4*)&g_Q[r * 512 + h * 64 + k0 + k8 + 4];
            As[k8 + 0][r] = a0.x; As[k8 + 1][r] = a0.y; As[k8 + 2][r] = a0.z; As[k8 + 3][r] = a0.w;
            As[k8 + 4][r] = a1.x; As[k8 + 5][r] = a1.y; As[k8 + 6][r] = a1.z; As[k8 + 7][r] = a1.w;
        }
        {
            int kk = t >> 4, n8 = (t & 15) * 8;
            const float* src = &g_PET[(size_t)(h * 64 + k0 + kk) * 4096 + n0 + n8];
            *(float4*)&Bs[kk][n8]     = *(const float4*)&src[0];
            *(float4*)&Bs[kk][n8 + 4] = *(const float4*)&src[4];
        }
        __syncthreads();
        #pragma unroll
        for (int kk = 0; kk < 16; kk++) {
            float4 a0 = *(const float4*)&As[kk][tr * 8];
            float4 a1 = *(const float4*)&As[kk][tr * 8 + 4];
            float4 b0 = *(const float4*)&Bs[kk][tc * 8];
            float4 b1 = *(const float4*)&Bs[kk][tc * 8 + 4];
            float a[8] = {a0.x, a0.y, a0.z, a0.w, a1.x, a1.y, a1.z, a1.w};
            float bb[8] = {b0.x, b0.y, b0.z, b0.w, b1.x, b1.y, b1.z, b1.w};
            #pragma unroll
            for (int i = 0; i < 8; i++)
                #pragma unroll
                for (int j = 0; j < 8; j++) acc[i][j] += a[i] * bb[j];
        }
        __syncthreads();
    }
    #pragma unroll
    for (int i = 0; i < 8; i++) {
        int r = tr * 8 + i;
        int b = r >> 4, e = r & 15;
        float qb = g_QBK[(b * 8 + h) * 16 + e];
        float* dst = &g_S[(size_t)((b * 8 + h) * 16 + e) * 4096 + n0 + tc * 8];
        float4 o0 = make_float4(acc[i][0] + qb, acc[i][1] + qb, acc[i][2] + qb, acc[i][3] + qb);
        float4 o1 = make_float4(acc[i][4] + qb, acc[i][5] + qb, acc[i][6] + qb, acc[i][7] + qb);
        *(float4*)&dst[0] = o0; *(float4*)&dst[4] = o1;
    }
}

// ---------------- K6: scores: g_S += rinv(n) * (tq' @ X) -------------------------
// grid(32 ntile, 8 b), 256 thr, M=128(he) x N=128(n) x K=256
__global__ void __launch_bounds__(256) k_scores(const float* __restrict__ X) {
    __shared__ float As[16][128];
    __shared__ float Bs[16][128];
    int n0 = blockIdx.x * 128, b = blockIdx.y, t = threadIdx.x;
    int tr = t >> 4, tc = t & 15;
    const float* Xb = X + (size_t)b * CC * NN;
    const float* TQ = g_TQ + (size_t)b * 128 * 256;
    float acc[8][8];
    #pragma unroll
    for (int i = 0; i < 8; i++)
        #pragma unroll
        for (int j = 0; j < 8; j++) acc[i][j] = 0.f;
    for (int c0 = 0; c0 < 256; c0 += 16) {
        {
            int r = t >> 1, k8 = (t & 1) * 8;
            float4 a0 = *(const float4*)&TQ[r * 256 + c0 + k8];
            float4 a1 = *(const float4*)&TQ[r * 256 + c0 + k8 + 4];
            As[k8 + 0][r] = a0.x; As[k8 + 1][r] = a0.y; As[k8 + 2][r] = a0.z; As[k8 + 3][r] = a0.w;
            As[k8 + 4][r] = a1.x; As[k8 + 5][r] = a1.y; As[k8 + 6][r] = a1.z; As[k8 + 7][r] = a1.w;
        }
        {
            int kk = t >> 4, n8 = (t & 15) * 8;
            const float* src = &Xb[(size_t)(c0 + kk) * 4096 + n0 + n8];
            *(float4*)&Bs[kk][n8]     = *(const float4*)&src[0];
            *(float4*)&Bs[kk][n8 + 4] = *(const float4*)&src[4];
        }
        __syncthreads();
        #pragma unroll
        for (int kk = 0; kk < 16; kk++) {
            float4 a0 = *(const float4*)&As[kk][tr * 8];
            float4 a1 = *(const float4*)&As[kk][tr * 8 + 4];
            float4 b0 = *(const float4*)&Bs[kk][tc * 8];
            float4 b1 = *(const float4*)&Bs[kk][tc * 8 + 4];
            float a[8] = {a0.x, a0.y, a0.z, a0.w, a1.x, a1.y, a1.z, a1.w};
            float bb[8] = {b0.x, b0.y, b0.z, b0.w, b1.x, b1.y, b1.z, b1.w};
            #pragma unroll
            for (int i = 0; i < 8; i++)
                #pragma unroll
                for (int j = 0; j < 8; j++) acc[i][j] += a[i] * bb[j];
        }
        __syncthreads();
    }
    float4 rv0 = *(const float4*)&g_RINV[b * 4096 + n0 + tc * 8];
    float4 rv1 = *(const float4*)&g_RINV[b * 4096 + n0 + tc * 8 + 4];
    float rv[8] = {rv0.x, rv0.y, rv0.z, rv0.w, rv1.x, rv1.y, rv1.z, rv1.w};
    #pragma unroll
    for (int i = 0; i < 8; i++) {
        int r = tr * 8 + i;
        float* dst = &g_S[(size_t)(b * 128 + r) * 4096 + n0 + tc * 8];
        float4 e0 = *(const float4*)&dst[0];
        float4 e1 = *(const float4*)&dst[4];
        // scale = HEAD_DIM^-0.5 = 0.125 applied here to whole score
        e0.x = (e0.x + acc[i][0] * rv[0]) * 0.125f;
        e0.y = (e0.y + acc[i][1] * rv[1]) * 0.125f;
        e0.z = (e0.z + acc[i][2] * rv[2]) * 0.125f;
        e0.w = (e0.w + acc[i][3] * rv[3]) * 0.125f;
        e1.x = (e1.x + acc[i][4] * rv[4]) * 0.125f;
        e1.y = (e1.y + acc[i][5] * rv[5]) * 0.125f;
        e1.z = (e1.z + acc[i][6] * rv[6]) * 0.125f;
        e1.w = (e1.w + acc[i][7] * rv[7]) * 0.125f;
        *(float4*)&dst[0] = e0; *(float4*)&dst[4] = e1;
    }
}

// ---------------- K7: softmax over n=4096 -----------------------------------------
__global__ void k_softmax() {
    __shared__ float red[32];
    int row = blockIdx.x;
    float* s = g_S + (size_t)row * NN;
    int t = threadIdx.x;  // 256
    float loc[16];
    float m = -1e30f;
    #pragma unroll
    for (int i = 0; i < 16; i++) { loc[i] = s[t + i * 256]; m = fmaxf(m, loc[i]); }
    m = blk_red<8, true>(m, red);
    float sum = 0.0f;
    #pragma unroll
    for (int i = 0; i < 16; i++) { loc[i] = expf(loc[i] - m); sum += loc[i]; }
    sum = blk_red<8, false>(sum, red);
    float inv = 1.0f / sum;
    #pragma unroll
    for (int i = 0; i < 16; i++) s[t + i * 256] = loc[i] * inv;
}

// ---------------- K8: pa partials: (p*rinv) @ X^T ---------------------------------
// grid(16 ksplit, 8 b), 512 thr, M=128(he) x N=256(c) x Kchunk=256(n)
__global__ void __launch_bounds__(512) k_pa(const float* __restrict__ X) {
    __shared__ float As[16][128];
    __shared__ float Bs[16][256];
    int ks = blockIdx.x, b = blockIdx.y, t = threadIdx.x;
    int nbase = ks * 256;
    int tr = t >> 5, tc = t & 31;
    const float* Xb = X + (size_t)b * CC * NN;
    float acc[8][8];
    #pragma unroll
    for (int i = 0; i < 8; i++)
        #pragma unroll
        for (int j = 0; j < 8; j++) acc[i][j] = 0.f;
    for (int k0 = 0; k0 < 256; k0 += 16) {
        {
            int he = t >> 2, k4 = (t & 3) * 4;
            int n = nbase + k0 + k4;
            float4 p  = *(const float4*)&g_S[(size_t)(b * 128 + he) * 4096 + n];
            float4 rv = *(const float4*)&g_RINV[b * 4096 + n];
            As[k4 + 0][he] = p.x * rv.x;
            As[k4 + 1][he] = p.y * rv.y;
            As[k4 + 2][he] = p.z * rv.z;
            As[k4 + 3][he] = p.w * rv.w;
        }
        {
            int c = t >> 1, k8 = (t & 1) * 8;
            const float* src = &Xb[(size_t)c * 4096 + nbase + k0 + k8];
            float4 v0 = *(const float4*)&src[0];
            float4 v1 = *(const float4*)&src[4];
            Bs[k8 + 0][c] = v0.x; Bs[k8 + 1][c] = v0.y; Bs[k8 + 2][c] = v0.z; Bs[k8 + 3][c] = v0.w;
            Bs[k8 + 4][c] = v1.x; Bs[k8 + 5][c] = v1.y; Bs[k8 + 6][c] = v1.z; Bs[k8 + 7][c] = v1.w;
        }
        __syncthreads();
        #pragma unroll
        for (int kk = 0; kk < 16; kk++) {
            float4 a0 = *(const float4*)&As[kk][tr * 8];
            float4 a1 = *(const float4*)&As[kk][tr * 8 + 4];
            float4 b0 = *(const float4*)&Bs[kk][tc * 8];
            float4 b1 = *(const float4*)&Bs[kk][tc * 8 + 4];
            float a[8] = {a0.x, a0.y, a0.z, a0.w, a1.x, a1.y, a1.z, a1.w};
            float bb[8] = {b0.x, b0.y, b0.z, b0.w, b1.x, b1.y, b1.z, b1.w};
            #pragma unroll
            for (int i = 0; i < 8; i++)
                #pragma unroll
                for (int j = 0; j < 8; j++) acc[i][j] += a[i] * bb[j];
        }
        __syncthreads();
    }
    #pragma unroll
    for (int i = 0; i < 8; i++) {
        int he = tr * 8 + i;
        float* dst = &g_PAP[(size_t)((ks * 8 + b) * 128 + he) * 256 + tc * 8];
        *(float4*)&dst[0] = make_float4(acc[i][0], acc[i][1], acc[i][2], acc[i][3]);
        *(float4*)&dst[4] = make_float4(acc[i][4], acc[i][5], acc[i][6], acc[i][7]);
    }
}

// ---------------- K9: ope partials: p @ pe (h-slice) ------------------------------
// grid(64 bh, 4 ksplit), 256 thr
__global__ void __launch_bounds__(256) k_ppe() {
    int bh = blockIdx.x, ks = blockIdx.y, t = threadIdx.x;
    int h = bh & 7;
    int e0 = (t >> 6) * 4, d = t & 63;
    int n0 = ks * 1024;
    const float* PEp = &g_PE[(size_t)n0 * 512 + h * 64 + d];
    const float* Sp  = &g_S[(size_t)(bh * 16 + e0) * 4096 + n0];
    float a0 = 0.f, a1 = 0.f, a2 = 0.f, a3 = 0.f;
    #pragma unroll 4
    for (int n = 0; n < 1024; n++) {
        float pe = PEp[(size_t)n * 512];
        a0 += Sp[n] * pe;
        a1 += Sp[4096 + n] * pe;
        a2 += Sp[8192 + n] * pe;
        a3 += Sp[12288 + n] * pe;
    }
    int base = ((ks * 64 + bh) * 16 + e0) * 64 + d;
    g_OPEP[base]       = a0;
    g_OPEP[base + 64]  = a1;
    g_OPEP[base + 128] = a2;
    g_OPEP[base + 192] = a3;
}

// ---------------- K10: out0 = (pa*wp) @ Wv + ope + bv -----------------------------
// grid(32), 512 thr, 4 rows x 512 cols, K=256 split 4 ways
__global__ void __launch_bounds__(512) k_out(const float* __restrict__ wkv,
                                             const float* __restrict__ bkv,
                                             const float* __restrict__ wp) {
    __shared__ float pool[8192];     // pa_s[4][8][256] then part[4][4][512]
    __shared__ float ope_s[4][512];
    int row0 = blockIdx.x * 4;
    int t = threadIdx.x;
    for (int idx = t; idx < 8192; idx += 512) {
        int r = idx >> 11, rest = idx & 2047, h = rest >> 8, c = rest & 255;
        int row = row0 + r, b = row >> 4, e = row & 15;
        float s = 0.f;
        #pragma unroll
        for (int ks = 0; ks < 16; ks++)
            s += g_PAP[(size_t)((ks * 8 + b) * 128 + h * 16 + e) * 256 + c];
        pool[idx] = s * wp[c];
    }
    for (int idx = t; idx < 2048; idx += 512) {
        int r = idx >> 9, j = idx & 511;
        int row = row0 + r, b = row >> 4, e = row & 15;
        int h = j >> 6, d = j & 63;
        float s = 0.f;
        #pragma unroll
        for (int ks = 0; ks < 4; ks++)
            s += g_OPEP[((ks * 64 + b * 8 + h) * 16 + e) * 64 + d];
        ope_s[r][j] = s;
    }
    __syncthreads();
    int tj = t & 127, tk = t >> 7;
    int h = tj >> 4;
    float4 acc[4];
    #pragma unroll
    for (int r = 0; r < 4; r++) acc[r] = make_float4(0.f, 0.f, 0.f, 0.f);
    #pragma unroll 4
    for (int c = tk * 64; c < tk * 64 + 64; c++) {
        float4 w4 = *(const float4*)&wkv[(size_t)c * 1024 + 512 + tj * 4];
        #pragma unroll
        for (int r = 0; r < 4; r++) {
            float p = pool[r * 2048 + h * 256 + c];
            acc[r].x += p * w4.x; acc[r].y += p * w4.y;
            acc[r].z += p * w4.z; acc[r].w += p * w4.w;
        }
    }
    __syncthreads();
    #pragma unroll
    for (int r = 0; r < 4; r++) *(float4*)&pool[(tk * 4 + r) * 512 + tj * 4] = acc[r];
    __syncthreads();
    {
        int r = t >> 7, j0 = (t & 127) * 4;
        float4 s = make_float4(0.f, 0.f, 0.f, 0.f);
        #pragma unroll
        for (int k2 = 0; k2 < 4; k2++) {
            float4 p = *(const float4*)&pool[(k2 * 4 + r) * 512 + j0];
            s.x += p.x; s.y += p.y; s.z += p.z; s.w += p.w;
        }
        float4 bv = *(const float4*)&bkv[512 + j0];
        float4 op = *(const float4*)&ope_s[r][j0];
        s.x += bv.x + op.x; s.y += bv.y + op.y;
        s.z += bv.z + op.z; s.w += bv.w + op.w;
        *(float4*)&g_ATT0[(row0 + r) * 512 + j0] = s;
    }
}

// ---------------- K11: proj + residual --------------------------------------------
// grid(16, 4), 256 thr, 8 rows x 128 cols, K=512 split 8 ways
__global__ void __launch_bounds__(256) k_proj(const float* __restrict__ wproj,
                                              const float* __restrict__ bproj) {
    __shared__ float x_s[8][512];
    __shared__ float part[8][8][128];
    int row0 = blockIdx.x * 8, jb = blockIdx.y * 128, t = threadIdx.x;
    for (int idx = t; idx < 4096; idx += 256)
        x_s[idx >> 9][idx & 511] = g_ATT0[(row0 + (idx >> 9)) * 512 + (idx & 511)];
    __syncthreads();
    int tk = t >> 5, tj = t & 31, j = jb + tj * 4;
    float4 acc[8];
    #pragma unroll
    for (int r = 0; r < 8; r++) acc[r] = make_float4(0.f, 0.f, 0.f, 0.f);
    #pragma unroll 4
    for (int c = tk * 64; c < tk * 64 + 64; c++) {
        float4 w4 = *(const float4*)&wproj[(size_t)c * 512 + j];
        #pragma unroll
        for (int r = 0; r < 8; r++) {
            float x = x_s[r][c];
            acc[r].x += x * w4.x; acc[r].y += x * w4.y;
            acc[r].z += x * w4.z; acc[r].w += x * w4.w;
        }
    }
    #pragma unroll
    for (int r = 0; r < 8; r++) *(float4*)&part[tk][r][tj * 4] = acc[r];
    __syncthreads();
    {
        int r = t >> 5, cq = t & 31, j2 = jb + cq * 4;
        float4 s = make_float4(0.f, 0.f, 0.f, 0.f);
        #pragma unroll
        for (int k2 = 0; k2 < 8; k2++) {
            float4 p = *(const float4*)&part[k2][r][cq * 4];
            s.x += p.x; s.y += p.y; s.z += p.z; s.w += p.w;
        }
        float4 bp = *(const float4*)&bproj[j2];
        float4 mn = *(const float4*)&g_MOLN[(row0 + r) * 512 + j2];
        s.x += bp.x + mn.x; s.y += bp.y + mn.y;
        s.z += bp.z + mn.z; s.w += bp.w + mn.w;
        *(float4*)&g_ATT[(row0 + r) * 512 + j2] = s;
    }
}

// ---------------- K12: ffn rmsnorm -------------------------------------------------
__global__ void k_ffnorm(const float* __restrict__ nw) {
    __shared__ float red[32];
    int row = blockIdx.x, t = threadIdx.x;  // 512
    float x = g_ATT[row * 512 + t];
    float ss = blk_red<16, false>(x * x, red);
    g_ATTN[row * 512 + t] = x * rsqrtf(ss * (1.0f / 512.0f) + EPSV) * nw[t];
}

// ---------------- K13: ffn1 + gelu -------------------------------------------------
// grid(16, 16), 256 thr, 8 rows x 128 cols, K=512 split 8 ways
__global__ void __launch_bounds__(256) k_ffn1(const float* __restrict__ w1,
                                              const float* __restrict__ b1) {
    __shared__ float x_s[8][512];
    __shared__ float part[8][8][128];
    int row0 = blockIdx.x * 8, jb = blockIdx.y * 128, t = threadIdx.x;
    for (int idx = t; idx < 4096; idx += 256)
        x_s[idx >> 9][idx & 511] = g_ATTN[(row0 + (idx >> 9)) * 512 + (idx & 511)];
    __syncthreads();
    int tk = t >> 5, tj = t & 31, j = jb + tj * 4;
    float4 acc[8];
    #pragma unroll
    for (int r = 0; r < 8; r++) acc[r] = make_float4(0.f, 0.f, 0.f, 0.f);
    #pragma unroll 4
    for (int c = tk * 64; c < tk * 64 + 64; c++) {
        float4 w4 = *(const float4*)&w1[(size_t)c * 2048 + j];
        #pragma unroll
        for (int r = 0; r < 8; r++) {
            float x = x_s[r][c];
            acc[r].x += x * w4.x; acc[r].y += x * w4.y;
            acc[r].z += x * w4.z; acc[r].w += x * w4.w;
        }
    }
    #pragma unroll
    for (int r = 0; r < 8; r++) *(float4*)&part[tk][r][tj * 4] = acc[r];
    __syncthreads();
    {
        int r = t >> 5, cq = t & 31, j2 = jb + cq * 4;
        float4 s = make_float4(0.f, 0.f, 0.f, 0.f);
        #pragma unroll
        for (int k2 = 0; k2 < 8; k2++) {
            float4 p = *(const float4*)&part[k2][r][cq * 4];
            s.x += p.x; s.y += p.y; s.z += p.z; s.w += p.w;
        }
        float4 bb = *(const float4*)&b1[j2];
        float4 o;
        o.x = geluf(s.x + bb.x); o.y = geluf(s.y + bb.y);
        o.z = geluf(s.z + bb.z); o.w = geluf(s.w + bb.w);
        *(float4*)&g_H1[(size_t)(row0 + r) * 2048 + j2] = o;
    }
}

// ---------------- K14: ffn2 + residual ---------------------------------------------
// grid(32, 4), 512 thr, 4 rows x 128 cols, K=2048 split 16 ways
__global__ void __launch_bounds__(512) k_ffn2(const float* __restrict__ w2,
                                              const float* __restrict__ b2,
                                              float* __restrict__ out) {
    __shared__ float pool[8192];  // h_s[4][2048] then part[16][4][128]
    int row0 = blockIdx.x * 4, jb = blockIdx.y * 128, t = threadIdx.x;
    for (int idx = t; idx < 8192; idx += 512)
        pool[idx] = g_H1[(size_t)(row0 + (idx >> 11)) * 2048 + (idx & 2047)];
    __syncthreads();
    int tk = t >> 5, tj = t & 31, j = jb + tj * 4;
    float4 acc[4];
    #pragma unroll
    for (int r = 0; r < 4; r++) acc[r] = make_float4(0.f, 0.f, 0.f, 0.f);
    #pragma unroll 4
    for (int c = tk * 128; c < tk * 128 + 128; c++) {
        float4 w4 = *(const float4*)&w2[(size_t)c * 512 + j];
        #pragma unroll
        for (int r = 0; r < 4; r++) {
            float x = pool[r * 2048 + c];
            acc[r].x += x * w4.x; acc[r].y += x * w4.y;
            acc[r].z += x * w4.z; acc[r].w += x * w4.w;
        }
    }
    __syncthreads();
    #pragma unroll
    for (int r = 0; r < 4; r++) *(float4*)&pool[tk * 512 + r * 128 + tj * 4] = acc[r];
    __syncthreads();
    {
        int r = t >> 7, cq = t & 127;
        float s = 0.f;
        #pragma unroll
        for (int k2 = 0; k2 < 16; k2++) s += pool[k2 * 512 + r * 128 + cq];
        int j2 = jb + cq;
        out[(row0 + r) * 512 + j2] = s + b2[j2] + g_ATT[(row0 + r) * 512 + j2];
    }
}

// ---------------- launch ------------------------------------------------------------
extern "C" void kernel_launch(void* const* d_in, const int* in_sizes, int n_in,
                              void* d_out, int out_size) {
    const float* patch   = (const float*)d_in[0];
    const float* mol     = (const float*)d_in[1];
    const float* pe_w1   = (const float*)d_in[2];
    const float* pe_b1   = (const float*)d_in[3];
    const float* pe_w2   = (const float*)d_in[4];
    const float* pe_b2   = (const float*)d_in[5];
    const float* wq      = (const float*)d_in[6];
    const float* bq      = (const float*)d_in[7];
    const float* wkv     = (const float*)d_in[8];
    const float* bkv     = (const float*)d_in[9];
    const float* wproj   = (const float*)d_in[10];
    const float* bproj   = (const float*)d_in[11];
    const float* nmolw   = (const float*)d_in[12];
    const float* npatchw = (const float*)d_in[13];
    const float* ffn_w1  = (const float*)d_in[14];
    const float* ffn_b1  = (const float*)d_in[15];
    const float* ffn_w2  = (const float*)d_in[16];
    const float* ffn_b2  = (const float*)d_in[17];
    const float* ffn_nw  = (const float*)d_in[18];
    float* out = (float*)d_out;
    (void)in_sizes; (void)n_in; (void)out_size;

    k_pos    <<<NN / 16, 256>>>(pe_w1, pe_b1, pe_w2, pe_b2);
    k_rinv   <<<(BB * NN) / 256, 256>>>(patch);
    k_molq   <<<dim3(16, 4), 256>>>(mol, nmolw, wq, bq);
    k_tq     <<<dim3(8, 8), 256>>>(wkv, bkv, npatchw);
    k_qpe    <<<dim3(32, 8), 256>>>();
    k_scores <<<dim3(32, 8), 256>>>(patch);
    k_softmax<<<BB * 128, 256>>>();
    k_pa     <<<dim3(16, 8), 512>>>(patch);
    k_ppe    <<<dim3(64, 4), 256>>>();
    k_out    <<<32, 512>>>(wkv, bkv, npatchw);
    k_proj   <<<dim3(16, 4), 256>>>(wproj, bproj);
    k_ffnorm <<<128, 512>>>(ffn_nw);
    k_ffn1   <<<dim3(16, 16), 256>>>(ffn_w1, ffn_b1);
    k_ffn2   <<<dim3(32, 4), 512>>>(ffn_w2, ffn_b2, out);
}

// round 7
// speedup vs baseline: 3.5935x; 1.5755x over previous
#include <cuda_runtime.h>
#include <math.h>

#define BB 8
#define CC 256
#define NN 4096
#define MM 512
#define EE 16
#define NH 8
#define FFNH 2048
#define EPSV 1.1920929e-07f

// ------------- scratch (__device__ globals; no allocation allowed) ---------------
__device__ float g_G   [NN * 256];            // gelu hidden of pos MLP   4 MB
__device__ float g_PE  [NN * MM];             // pos_enc [n][512]         8 MB
__device__ float g_RINV[BB * NN];             // patch rmsnorm rsqrt
__device__ float g_Q   [128 * 512];           // q rows=(b,e)
__device__ float g_MOLN[128 * 512];           // normalized mol (residual)
__device__ float g_TQ  [BB * 128 * 256];      // tq' rows=(b, h*16+e), wp folded
__device__ float g_QBK [BB * NH * EE];        // q . bk  (per b,h,e)
__device__ float g_S   [(size_t)BB * 128 * NN];       // scores/probs  16.8 MB
__device__ float g_PAP [(size_t)16 * BB * 128 * 256]; // pa partials   16.8 MB
__device__ float g_OPEP[8 * 8 * 128 * 64];    // p@pe partials 2 MB: [(ks*8+h)*128+(b*16+e)]*64+d
__device__ float g_ATT0[128 * 512];           // attention out (pre-proj)
__device__ float g_ATT [128 * 512];           // attended (post residual)
__device__ float g_H1  [128 * 2048];          // ffn hidden

__device__ __forceinline__ float geluf(float x) {
    return 0.5f * x * (1.0f + erff(x * 0.70710678118654752440f));
}

template <int NWARPS, bool DOMAX>
__device__ __forceinline__ float blk_red(float v, float* red) {
    #pragma unroll
    for (int o = 16; o; o >>= 1) {
        float t = __shfl_xor_sync(0xffffffffu, v, o);
        v = DOMAX ? fmaxf(v, t) : v + t;
    }
    if ((threadIdx.x & 31) == 0) red[threadIdx.x >> 5] = v;
    __syncthreads();
    if (threadIdx.x < 32) {
        float r = (threadIdx.x < NWARPS) ? red[threadIdx.x] : (DOMAX ? -1e30f : 0.0f);
        #pragma unroll
        for (int o = NWARPS >> 1; o; o >>= 1) {
            float t = __shfl_xor_sync(0xffffffffu, r, o);
            r = DOMAX ? fmaxf(r, t) : r + t;
        }
        if (threadIdx.x == 0) red[0] = r;
    }
    __syncthreads();
    float s = red[0];
    __syncthreads();
    return s;
}

// ---------------- K1a: G = gelu(coords @ W1 + b1)  [4096, 256] --------------------
__global__ void k_gel(const float* __restrict__ w1, const float* __restrict__ b1) {
    int n = blockIdx.x, k = threadIdx.x;  // 256
    float cd = (float)(n >> 8)        * 0.0625f;
    float ch = (float)((n >> 4) & 15) * 0.0625f;
    float cw = (float)(n & 15)        * 0.0625f;
    g_G[n * 256 + k] = geluf(cd * w1[k] + ch * w1[256 + k] + cw * w1[512 + k] + b1[k]);
}

// ---------------- K1b: PE = G @ W2 + b2  (M=4096, N=512, K=256) -------------------
// grid(32 m, 4 j), 256 thr, tile 128x128, micro 8x8
__global__ void __launch_bounds__(256) k_peg(const float* __restrict__ w2,
                                             const float* __restrict__ b2) {
    __shared__ float As[16][128];
    __shared__ float Bs[16][128];
    int m0 = blockIdx.x * 128, j0 = blockIdx.y * 128, t = threadIdx.x;
    int tr = t >> 4, tc = t & 15;
    float acc[8][8];
    #pragma unroll
    for (int i = 0; i < 8; i++)
        #pragma unroll
        for (int j = 0; j < 8; j++) acc[i][j] = 0.f;
    for (int k0 = 0; k0 < 256; k0 += 16) {
        {
            int r = t >> 1, k8 = (t & 1) * 8;
            float4 a0 = *(const float4*)&g_G[(m0 + r) * 256 + k0 + k8];
            float4 a1 = *(const float4*)&g_G[(m0 + r) * 256 + k0 + k8 + 4];
            As[k8 + 0][r] = a0.x; As[k8 + 1][r] = a0.y; As[k8 + 2][r] = a0.z; As[k8 + 3][r] = a0.w;
            As[k8 + 4][r] = a1.x; As[k8 + 5][r] = a1.y; As[k8 + 6][r] = a1.z; As[k8 + 7][r] = a1.w;
        }
        {
            int kk = t >> 4, j8 = (t & 15) * 8;
            const float* src = &w2[(size_t)(k0 + kk) * 512 + j0 + j8];
            *(float4*)&Bs[kk][j8]     = *(const float4*)&src[0];
            *(float4*)&Bs[kk][j8 + 4] = *(const float4*)&src[4];
        }
        __syncthreads();
        #pragma unroll
        for (int kk = 0; kk < 16; kk++) {
            float4 a0 = *(const float4*)&As[kk][tr * 8];
            float4 a1 = *(const float4*)&As[kk][tr * 8 + 4];
            float4 b0 = *(const float4*)&Bs[kk][tc * 8];
            float4 b1 = *(const float4*)&Bs[kk][tc * 8 + 4];
            float a[8] = {a0.x, a0.y, a0.z, a0.w, a1.x, a1.y, a1.z, a1.w};
            float bb[8] = {b0.x, b0.y, b0.z, b0.w, b1.x, b1.y, b1.z, b1.w};
            #pragma unroll
            for (int i = 0; i < 8; i++)
                #pragma unroll
                for (int j = 0; j < 8; j++) acc[i][j] += a[i] * bb[j];
        }
        __syncthreads();
    }
    float4 bv0 = *(const float4*)&b2[j0 + tc * 8];
    float4 bv1 = *(const float4*)&b2[j0 + tc * 8 + 4];
    #pragma unroll
    for (int i = 0; i < 8; i++) {
        float* dst = &g_PE[(size_t)(m0 + tr * 8 + i) * 512 + j0 + tc * 8];
        *(float4*)&dst[0] = make_float4(acc[i][0] + bv0.x, acc[i][1] + bv0.y,
                                        acc[i][2] + bv0.z, acc[i][3] + bv0.w);
        *(float4*)&dst[4] = make_float4(acc[i][4] + bv1.x, acc[i][5] + bv1.y,
                                        acc[i][6] + bv1.z, acc[i][7] + bv1.w);
    }
}

// ---------------- K2: patch rmsnorm rsqrt factor ---------------------------------
__global__ void k_rinv(const float* __restrict__ X) {
    int t = blockIdx.x * blockDim.x + threadIdx.x;
    int b = t >> 12, n = t & (NN - 1);
    const float* p = X + (size_t)b * CC * NN + n;
    float s = 0.0f;
    #pragma unroll 8
    for (int c = 0; c < CC; c++) { float v = p[(size_t)c * NN]; s += v * v; }
    g_RINV[t] = rsqrtf(s * (1.0f / 256.0f) + EPSV);
}

// ---------------- K3: mol rmsnorm + Q projection ----------------------------------
__global__ void __launch_bounds__(256) k_molq(const float* __restrict__ mol,
                                              const float* __restrict__ wmol,
                                              const float* __restrict__ wq,
                                              const float* __restrict__ bq) {
    __shared__ float x_s[8][512];
    __shared__ float part[8][8][128];
    int row0 = blockIdx.x * 8, jb = blockIdx.y * 128;
    int t = threadIdx.x;
    int w = t >> 5, lane = t & 31;
    float vals[16]; float ss = 0.0f;
    #pragma unroll
    for (int i = 0; i < 16; i++) {
        float v = mol[(row0 + w) * 512 + lane + i * 32];
        vals[i] = v; ss += v * v;
    }
    #pragma unroll
    for (int o = 16; o; o >>= 1) ss += __shfl_xor_sync(0xffffffffu, ss, o);
    float rv = rsqrtf(ss * (1.0f / 512.0f) + EPSV);
    #pragma unroll
    for (int i = 0; i < 16; i++) {
        int m = lane + i * 32;
        float xn = vals[i] * rv * wmol[m];
        x_s[w][m] = xn;
        if (blockIdx.y == 0) g_MOLN[(row0 + w) * 512 + m] = xn;
    }
    __syncthreads();
    int tk = w, tj = lane, j = jb + tj * 4;
    float4 acc[8];
    #pragma unroll
    for (int r = 0; r < 8; r++) acc[r] = make_float4(0.f, 0.f, 0.f, 0.f);
    #pragma unroll 4
    for (int c = tk * 64; c < tk * 64 + 64; c++) {
        float4 w4 = *(const float4*)&wq[(size_t)c * 512 + j];
        #pragma unroll
        for (int r = 0; r < 8; r++) {
            float x = x_s[r][c];
            acc[r].x += x * w4.x; acc[r].y += x * w4.y;
            acc[r].z += x * w4.z; acc[r].w += x * w4.w;
        }
    }
    #pragma unroll
    for (int r = 0; r < 8; r++) *(float4*)&part[tk][r][tj * 4] = acc[r];
    __syncthreads();
    {
        int r = t >> 5, cq = t & 31, j2 = jb + cq * 4;
        float4 s = make_float4(0.f, 0.f, 0.f, 0.f);
        #pragma unroll
        for (int k2 = 0; k2 < 8; k2++) {
            float4 p = *(const float4*)&part[k2][r][cq * 4];
            s.x += p.x; s.y += p.y; s.z += p.z; s.w += p.w;
        }
        float4 bv = *(const float4*)&bq[j2];
        s.x += bv.x; s.y += bv.y; s.z += bv.z; s.w += bv.w;
        *(float4*)&g_Q[(row0 + r) * 512 + j2] = s;
    }
}

// ---------------- K4: qbk[b,h,e] = q . bkv(h-slice) -------------------------------
__global__ void k_qbk(const float* __restrict__ bkv) {
    int t = blockIdx.x * 256 + threadIdx.x;  // 0..1023
    int b = t >> 7, h = (t >> 4) & 7, e = t & 15;
    float s = 0.f;
    #pragma unroll
    for (int d = 0; d < 64; d++) s += g_Q[(b * 16 + e) * 512 + h * 64 + d] * bkv[h * 64 + d];
    g_QBK[(b * 8 + h) * 16 + e] = s;
}

// ---------------- K5: tq'[b,h,e,c] = wp[c]*(q_h . Wk_h[c,:]) as GEMM --------------
// grid(8 h, 2 cb), 256 thr, M=128(b,e) x N=128(c) x K=64
__global__ void __launch_bounds__(256) k_tq2(const float* __restrict__ wkv,
                                             const float* __restrict__ wp) {
    __shared__ float As[16][128];
    __shared__ float Bs[16][128];
    int h = blockIdx.x, c0b = blockIdx.y * 128, t = threadIdx.x;
    int tr = t >> 4, tc = t & 15;
    float acc[8][8];
    #pragma unroll
    for (int i = 0; i < 8; i++)
        #pragma unroll
        for (int j = 0; j < 8; j++) acc[i][j] = 0.f;
    for (int k0 = 0; k0 < 64; k0 += 16) {
        {
            int r = t >> 1, k8 = (t & 1) * 8;
            int b = r >> 4, e = r & 15;
            const float* src = &g_Q[(b * 16 + e) * 512 + h * 64 + k0 + k8];
            float4 a0 = *(const float4*)&src[0];
            float4 a1 = *(const float4*)&src[4];
            As[k8 + 0][r] = a0.x; As[k8 + 1][r] = a0.y; As[k8 + 2][r] = a0.z; As[k8 + 3][r] = a0.w;
            As[k8 + 4][r] = a1.x; As[k8 + 5][r] = a1.y; As[k8 + 6][r] = a1.z; As[k8 + 7][r] = a1.w;
        }
        {
            int c = t >> 1, k8 = (t & 1) * 8;
            const float* src = &wkv[(size_t)(c0b + c) * 1024 + h * 64 + k0 + k8];
            float4 v0 = *(const float4*)&src[0];
            float4 v1 = *(const float4*)&src[4];
            Bs[k8 + 0][c] = v0.x; Bs[k8 + 1][c] = v0.y; Bs[k8 + 2][c] = v0.z; Bs[k8 + 3][c] = v0.w;
            Bs[k8 + 4][c] = v1.x; Bs[k8 + 5][c] = v1.y; Bs[k8 + 6][c] = v1.z; Bs[k8 + 7][c] = v1.w;
        }
        __syncthreads();
        #pragma unroll
        for (int kk = 0; kk < 16; kk++) {
            float4 a0 = *(const float4*)&As[kk][tr * 8];
            float4 a1 = *(const float4*)&As[kk][tr * 8 + 4];
            float4 b0 = *(const float4*)&Bs[kk][tc * 8];
            float4 b1 = *(const float4*)&Bs[kk][tc * 8 + 4];
            float a[8] = {a0.x, a0.y, a0.z, a0.w, a1.x, a1.y, a1.z, a1.w};
            float bb[8] = {b0.x, b0.y, b0.z, b0.w, b1.x, b1.y, b1.z, b1.w};
            #pragma unroll
            for (int i = 0; i < 8; i++)
                #pragma unroll
                for (int j = 0; j < 8; j++) acc[i][j] += a[i] * bb[j];
        }
        __syncthreads();
    }
    float4 wp0 = *(const float4*)&wp[c0b + tc * 8];
    float4 wp1 = *(const float4*)&wp[c0b + tc * 8 + 4];
    float wpv[8] = {wp0.x, wp0.y, wp0.z, wp0.w, wp1.x, wp1.y, wp1.z, wp1.w};
    #pragma unroll
    for (int i = 0; i < 8; i++) {
        int r = tr * 8 + i, b = r >> 4, e = r & 15;
        float* dst = &g_TQ[(size_t)(b * 128 + h * 16 + e) * 256 + c0b + tc * 8];
        #pragma unroll
        for (int j = 0; j < 8; j++) dst[j] = acc[i][j] * wpv[j];
    }
}

// ---------------- K6: S = q_h @ PE_h^T + qbk  (per h GEMM) -------------------------
// grid(32 nt, 8 h), 256 thr, M=128(b,e) x N=128(n) x K=64; PE loaded transposed
__global__ void __launch_bounds__(256) k_qpe2() {
    __shared__ float As[16][128];
    __shared__ float Bs[16][128];
    int n0 = blockIdx.x * 128, h = blockIdx.y, t = threadIdx.x;
    int tr = t >> 4, tc = t & 15;
    float acc[8][8];
    #pragma unroll
    for (int i = 0; i < 8; i++)
        #pragma unroll
        for (int j = 0; j < 8; j++) acc[i][j] = 0.f;
    for (int k0 = 0; k0 < 64; k0 += 16) {
        {
            int r = t >> 1, k8 = (t & 1) * 8;
            int b = r >> 4, e = r & 15;
            const float* src = &g_Q[(b * 16 + e) * 512 + h * 64 + k0 + k8];
            float4 a0 = *(const float4*)&src[0];
            float4 a1 = *(const float4*)&src[4];
            As[k8 + 0][r] = a0.x; As[k8 + 1][r] = a0.y; As[k8 + 2][r] = a0.z; As[k8 + 3][r] = a0.w;
            As[k8 + 4][r] = a1.x; As[k8 + 5][r] = a1.y; As[k8 + 6][r] = a1.z; As[k8 + 7][r] = a1.w;
        }
        {
            int nl = t >> 1, k8 = (t & 1) * 8;
            const float* src = &g_PE[(size_t)(n0 + nl) * 512 + h * 64 + k0 + k8];
            float4 v0 = *(const float4*)&src[0];
            float4 v1 = *(const float4*)&src[4];
            Bs[k8 + 0][nl] = v0.x; Bs[k8 + 1][nl] = v0.y; Bs[k8 + 2][nl] = v0.z; Bs[k8 + 3][nl] = v0.w;
            Bs[k8 + 4][nl] = v1.x; Bs[k8 + 5][nl] = v1.y; Bs[k8 + 6][nl] = v1.z; Bs[k8 + 7][nl] = v1.w;
        }
        __syncthreads();
        #pragma unroll
        for (int kk = 0; kk < 16; kk++) {
            float4 a0 = *(const float4*)&As[kk][tr * 8];
            float4 a1 = *(const float4*)&As[kk][tr * 8 + 4];
            float4 b0 = *(const float4*)&Bs[kk][tc * 8];
            float4 b1 = *(const float4*)&Bs[kk][tc * 8 + 4];
            float a[8] = {a0.x, a0.y, a0.z, a0.w, a1.x, a1.y, a1.z, a1.w};
            float bb[8] = {b0.x, b0.y, b0.z, b0.w, b1.x, b1.y, b1.z, b1.w};
            #pragma unroll
            for (int i = 0; i < 8; i++)
                #pragma unroll
                for (int j = 0; j < 8; j++) acc[i][j] += a[i] * bb[j];
        }
        __syncthreads();
    }
    #pragma unroll
    for (int i = 0; i < 8; i++) {
        int r = tr * 8 + i, b = r >> 4, e = r & 15;
        float qb = g_QBK[(b * 8 + h) * 16 + e];
        float* dst = &g_S[(size_t)((b * 8 + h) * 16 + e) * 4096 + n0 + tc * 8];
        *(float4*)&dst[0] = make_float4(acc[i][0] + qb, acc[i][1] + qb, acc[i][2] + qb, acc[i][3] + qb);
        *(float4*)&dst[4] = make_float4(acc[i][4] + qb, acc[i][5] + qb, acc[i][6] + qb, acc[i][7] + qb);
    }
}

// ---------------- K7: scores: S = (S + rinv(n)*(tq' @ X)) * 0.125 ------------------
// grid(32 nt, 8 b), 256 thr, M=128(he) x N=128(n) x K=256
__global__ void __launch_bounds__(256) k_scores(const float* __restrict__ X) {
    __shared__ float As[16][128];
    __shared__ float Bs[16][128];
    int n0 = blockIdx.x * 128, b = blockIdx.y, t = threadIdx.x;
    int tr = t >> 4, tc = t & 15;
    const float* Xb = X + (size_t)b * CC * NN;
    const float* TQ = g_TQ + (size_t)b * 128 * 256;
    float acc[8][8];
    #pragma unroll
    for (int i = 0; i < 8; i++)
        #pragma unroll
        for (int j = 0; j < 8; j++) acc[i][j] = 0.f;
    for (int c0 = 0; c0 < 256; c0 += 16) {
        {
            int r = t >> 1, k8 = (t & 1) * 8;
            float4 a0 = *(const float4*)&TQ[r * 256 + c0 + k8];
            float4 a1 = *(const float4*)&TQ[r * 256 + c0 + k8 + 4];
            As[k8 + 0][r] = a0.x; As[k8 + 1][r] = a0.y; As[k8 + 2][r] = a0.z; As[k8 + 3][r] = a0.w;
            As[k8 + 4][r] = a1.x; As[k8 + 5][r] = a1.y; As[k8 + 6][r] = a1.z; As[k8 + 7][r] = a1.w;
        }
        {
            int kk = t >> 4, n8 = (t & 15) * 8;
            const float* src = &Xb[(size_t)(c0 + kk) * 4096 + n0 + n8];
            *(float4*)&Bs[kk][n8]     = *(const float4*)&src[0];
            *(float4*)&Bs[kk][n8 + 4] = *(const float4*)&src[4];
        }
        __syncthreads();
        #pragma unroll
        for (int kk = 0; kk < 16; kk++) {
            float4 a0 = *(const float4*)&As[kk][tr * 8];
            float4 a1 = *(const float4*)&As[kk][tr * 8 + 4];
            float4 b0 = *(const float4*)&Bs[kk][tc * 8];
            float4 b1 = *(const float4*)&Bs[kk][tc * 8 + 4];
            float a[8] = {a0.x, a0.y, a0.z, a0.w, a1.x, a1.y, a1.z, a1.w};
            float bb[8] = {b0.x, b0.y, b0.z, b0.w, b1.x, b1.y, b1.z, b1.w};
            #pragma unroll
            for (int i = 0; i < 8; i++)
                #pragma unroll
                for (int j = 0; j < 8; j++) acc[i][j] += a[i] * bb[j];
        }
        __syncthreads();
    }
    float4 rv0 = *(const float4*)&g_RINV[b * 4096 + n0 + tc * 8];
    float4 rv1 = *(const float4*)&g_RINV[b * 4096 + n0 + tc * 8 + 4];
    float rv[8] = {rv0.x, rv0.y, rv0.z, rv0.w, rv1.x, rv1.y, rv1.z, rv1.w};
    #pragma unroll
    for (int i = 0; i < 8; i++) {
        int r = tr * 8 + i;
        float* dst = &g_S[(size_t)(b * 128 + r) * 4096 + n0 + tc * 8];
        float4 e0 = *(const float4*)&dst[0];
        float4 e1 = *(const float4*)&dst[4];
        e0.x = (e0.x + acc[i][0] * rv[0]) * 0.125f;
        e0.y = (e0.y + acc[i][1] * rv[1]) * 0.125f;
        e0.z = (e0.z + acc[i][2] * rv[2]) * 0.125f;
        e0.w = (e0.w + acc[i][3] * rv[3]) * 0.125f;
        e1.x = (e1.x + acc[i][4] * rv[4]) * 0.125f;
        e1.y = (e1.y + acc[i][5] * rv[5]) * 0.125f;
        e1.z = (e1.z + acc[i][6] * rv[6]) * 0.125f;
        e1.w = (e1.w + acc[i][7] * rv[7]) * 0.125f;
        *(float4*)&dst[0] = e0; *(float4*)&dst[4] = e1;
    }
}

// ---------------- K8: softmax over n=4096 ------------------------------------------
__global__ void k_softmax() {
    __shared__ float red[32];
    int row = blockIdx.x;
    float* s = g_S + (size_t)row * NN;
    int t = threadIdx.x;  // 256
    float loc[16];
    float m = -1e30f;
    #pragma unroll
    for (int i = 0; i < 16; i++) { loc[i] = s[t + i * 256]; m = fmaxf(m, loc[i]); }
    m = blk_red<8, true>(m, red);
    float sum = 0.0f;
    #pragma unroll
    for (int i = 0; i < 16; i++) { loc[i] = expf(loc[i] - m); sum += loc[i]; }
    sum = blk_red<8, false>(sum, red);
    float inv = 1.0f / sum;
    #pragma unroll
    for (int i = 0; i < 16; i++) s[t + i * 256] = loc[i] * inv;
}

// ---------------- K9: pa partials: (p*rinv) @ X^T ----------------------------------
__global__ void __launch_bounds__(512) k_pa(const float* __restrict__ X) {
    __shared__ float As[16][128];
    __shared__ float Bs[16][256];
    int ks = blockIdx.x, b = blockIdx.y, t = threadIdx.x;
    int nbase = ks * 256;
    int tr = t >> 5, tc = t & 31;
    const float* Xb = X + (size_t)b * CC * NN;
    float acc[8][8];
    #pragma unroll
    for (int i = 0; i < 8; i++)
        #pragma unroll
        for (int j = 0; j < 8; j++) acc[i][j] = 0.f;
    for (int k0 = 0; k0 < 256; k0 += 16) {
        {
            int he = t >> 2, k4 = (t & 3) * 4;
            int n = nbase + k0 + k4;
            float4 p  = *(const float4*)&g_S[(size_t)(b * 128 + he) * 4096 + n];
            float4 rv = *(const float4*)&g_RINV[b * 4096 + n];
            As[k4 + 0][he] = p.x * rv.x;
            As[k4 + 1][he] = p.y * rv.y;
            As[k4 + 2][he] = p.z * rv.z;
            As[k4 + 3][he] = p.w * rv.w;
        }
        {
            int c = t >> 1, k8 = (t & 1) * 8;
            const float* src = &Xb[(size_t)c * 4096 + nbase + k0 + k8];
            float4 v0 = *(const float4*)&src[0];
            float4 v1 = *(const float4*)&src[4];
            Bs[k8 + 0][c] = v0.x; Bs[k8 + 1][c] = v0.y; Bs[k8 + 2][c] = v0.z; Bs[k8 + 3][c] = v0.w;
            Bs[k8 + 4][c] = v1.x; Bs[k8 + 5][c] = v1.y; Bs[k8 + 6][c] = v1.z; Bs[k8 + 7][c] = v1.w;
        }
        __syncthreads();
        #pragma unroll
        for (int kk = 0; kk < 16; kk++) {
            float4 a0 = *(const float4*)&As[kk][tr * 8];
            float4 a1 = *(const float4*)&As[kk][tr * 8 + 4];
            float4 b0 = *(const float4*)&Bs[kk][tc * 8];
            float4 b1 = *(const float4*)&Bs[kk][tc * 8 + 4];
            float a[8] = {a0.x, a0.y, a0.z, a0.w, a1.x, a1.y, a1.z, a1.w};
            float bb[8] = {b0.x, b0.y, b0.z, b0.w, b1.x, b1.y, b1.z, b1.w};
            #pragma unroll
            for (int i = 0; i < 8; i++)
                #pragma unroll
                for (int j = 0; j < 8; j++) acc[i][j] += a[i] * bb[j];
        }
        __syncthreads();
    }
    #pragma unroll
    for (int i = 0; i < 8; i++) {
        int he = tr * 8 + i;
        float* dst = &g_PAP[(size_t)((ks * 8 + b) * 128 + he) * 256 + tc * 8];
        *(float4*)&dst[0] = make_float4(acc[i][0], acc[i][1], acc[i][2], acc[i][3]);
        *(float4*)&dst[4] = make_float4(acc[i][4], acc[i][5], acc[i][6], acc[i][7]);
    }
}

// ---------------- K10: ope partials: p @ PE_h  (per-h GEMM, K=4096 split 8) --------
// grid(8 h, 8 ks), 256 thr, M=128(b,e) x N=64(d) x Kchunk=512
__global__ void __launch_bounds__(256) k_ppe2() {
    __shared__ float As[16][128];
    __shared__ float Bs[16][64];
    int h = blockIdx.x, ks = blockIdx.y, t = threadIdx.x;
    int nb = ks * 512;
    int tr = t >> 4, tc = t & 15;
    float acc[8][4];
    #pragma unroll
    for (int i = 0; i < 8; i++)
        #pragma unroll
        for (int j = 0; j < 4; j++) acc[i][j] = 0.f;
    for (int k0 = 0; k0 < 512; k0 += 16) {
        {
            int r = t >> 1, k8 = (t & 1) * 8;
            int b = r >> 4, e = r & 15;
            const float* src = &g_S[(size_t)((b * 8 + h) * 16 + e) * 4096 + nb + k0 + k8];
            float4 v0 = *(const float4*)&src[0];
            float4 v1 = *(const float4*)&src[4];
            As[k8 + 0][r] = v0.x; As[k8 + 1][r] = v0.y; As[k8 + 2][r] = v0.z; As[k8 + 3][r] = v0.w;
            As[k8 + 4][r] = v1.x; As[k8 + 5][r] = v1.y; As[k8 + 6][r] = v1.z; As[k8 + 7][r] = v1.w;
        }
        {
            int kk = t >> 4, d4 = (t & 15) * 4;
            *(float4*)&Bs[kk][d4] = *(const float4*)&g_PE[(size_t)(nb + k0 + kk) * 512 + h * 64 + d4];
        }
        __syncthreads();
        #pragma unroll
        for (int kk = 0; kk < 16; kk++) {
            float4 a0 = *(const float4*)&As[kk][tr * 8];
            float4 a1 = *(const float4*)&As[kk][tr * 8 + 4];
            float4 b4 = *(const float4*)&Bs[kk][tc * 4];
            float a[8] = {a0.x, a0.y, a0.z, a0.w, a1.x, a1.y, a1.z, a1.w};
            float bb[4] = {b4.x, b4.y, b4.z, b4.w};
            #pragma unroll
            for (int i = 0; i < 8; i++)
                #pragma unroll
                for (int j = 0; j < 4; j++) acc[i][j] += a[i] * bb[j];
        }
        __syncthreads();
    }
    #pragma unroll
    for (int i = 0; i < 8; i++) {
        int r = tr * 8 + i;
        float* dst = &g_OPEP[(size_t)((ks * 8 + h) * 128 + r) * 64 + tc * 4];
        *(float4*)dst = make_float4(acc[i][0], acc[i][1], acc[i][2], acc[i][3]);
    }
}

// ---------------- K11: out0 = (pa*wp-reduced) @ Wv + ope + bv ----------------------
__global__ void __launch_bounds__(512) k_out(const float* __restrict__ wkv,
                                             const float* __restrict__ bkv,
                                             const float* __restrict__ wp) {
    __shared__ float pool[8192];     // pa_s[4][8][256] then part[4][4][512]
    __shared__ float ope_s[4][512];
    int row0 = blockIdx.x * 4;
    int t = threadIdx.x;
    for (int idx = t; idx < 8192; idx += 512) {
        int r = idx >> 11, rest = idx & 2047, h = rest >> 8, c = rest & 255;
        int row = row0 + r, b = row >> 4, e = row & 15;
        float s = 0.f;
        #pragma unroll
        for (int ks = 0; ks < 16; ks++)
            s += g_PAP[(size_t)((ks * 8 + b) * 128 + h * 16 + e) * 256 + c];
        pool[idx] = s * wp[c];
    }
    for (int idx = t; idx < 2048; idx += 512) {
        int r = idx >> 9, j = idx & 511;
        int row = row0 + r, b = row >> 4, e = row & 15;
        int h = j >> 6, d = j & 63;
        float s = 0.f;
        #pragma unroll
        for (int ks = 0; ks < 8; ks++)
            s += g_OPEP[(size_t)((ks * 8 + h) * 128 + b * 16 + e) * 64 + d];
        ope_s[r][j] = s;
    }
    __syncthreads();
    int tj = t & 127, tk = t >> 7;
    int h = tj >> 4;
    float4 acc[4];
    #pragma unroll
    for (int r = 0; r < 4; r++) acc[r] = make_float4(0.f, 0.f, 0.f, 0.f);
    #pragma unroll 4
    for (int c = tk * 64; c < tk * 64 + 64; c++) {
        float4 w4 = *(const float4*)&wkv[(size_t)c * 1024 + 512 + tj * 4];
        #pragma unroll
        for (int r = 0; r < 4; r++) {
            float p = pool[r * 2048 + h * 256 + c];
            acc[r].x += p * w4.x; acc[r].y += p * w4.y;
            acc[r].z += p * w4.z; acc[r].w += p * w4.w;
        }
    }
    __syncthreads();
    #pragma unroll
    for (int r = 0; r < 4; r++) *(float4*)&pool[(tk * 4 + r) * 512 + tj * 4] = acc[r];
    __syncthreads();
    {
        int r = t >> 7, j0 = (t & 127) * 4;
        float4 s = make_float4(0.f, 0.f, 0.f, 0.f);
        #pragma unroll
        for (int k2 = 0; k2 < 4; k2++) {
            float4 p = *(const float4*)&pool[(k2 * 4 + r) * 512 + j0];
            s.x += p.x; s.y += p.y; s.z += p.z; s.w += p.w;
        }
        float4 bv = *(const float4*)&bkv[512 + j0];
        float4 op = *(const float4*)&ope_s[r][j0];
        s.x += bv.x + op.x; s.y += bv.y + op.y;
        s.z += bv.z + op.z; s.w += bv.w + op.w;
        *(float4*)&g_ATT0[(row0 + r) * 512 + j0] = s;
    }
}

// ---------------- K12: proj + residual ---------------------------------------------
__global__ void __launch_bounds__(256) k_proj(const float* __restrict__ wproj,
                                              const float* __restrict__ bproj) {
    __shared__ float x_s[8][512];
    __shared__ float part[8][8][128];
    int row0 = blockIdx.x * 8, jb = blockIdx.y * 128, t = threadIdx.x;
    for (int idx = t; idx < 4096; idx += 256)
        x_s[idx >> 9][idx & 511] = g_ATT0[(row0 + (idx >> 9)) * 512 + (idx & 511)];
    __syncthreads();
    int tk = t >> 5, tj = t & 31, j = jb + tj * 4;
    float4 acc[8];
    #pragma unroll
    for (int r = 0; r < 8; r++) acc[r] = make_float4(0.f, 0.f, 0.f, 0.f);
    #pragma unroll 4
    for (int c = tk * 64; c < tk * 64 + 64; c++) {
        float4 w4 = *(const float4*)&wproj[(size_t)c * 512 + j];
        #pragma unroll
        for (int r = 0; r < 8; r++) {
            float x = x_s[r][c];
            acc[r].x += x * w4.x; acc[r].y += x * w4.y;
            acc[r].z += x * w4.z; acc[r].w += x * w4.w;
        }
    }
    #pragma unroll
    for (int r = 0; r < 8; r++) *(float4*)&part[tk][r][tj * 4] = acc[r];
    __syncthreads();
    {
        int r = t >> 5, cq = t & 31, j2 = jb + cq * 4;
        float4 s = make_float4(0.f, 0.f, 0.f, 0.f);
        #pragma unroll
        for (int k2 = 0; k2 < 8; k2++) {
            float4 p = *(const float4*)&part[k2][r][cq * 4];
            s.x += p.x; s.y += p.y; s.z += p.z; s.w += p.w;
        }
        float4 bp = *(const float4*)&bproj[j2];
        float4 mn = *(const float4*)&g_MOLN[(row0 + r) * 512 + j2];
        s.x += bp.x + mn.x; s.y += bp.y + mn.y;
        s.z += bp.z + mn.z; s.w += bp.w + mn.w;
        *(float4*)&g_ATT[(row0 + r) * 512 + j2] = s;
    }
}

// ---------------- K13: ffn1 (fused rmsnorm) + gelu ----------------------------------
__global__ void __launch_bounds__(256) k_ffn1(const float* __restrict__ nw,
                                              const float* __restrict__ w1,
                                              const float* __restrict__ b1) {
    __shared__ float x_s[8][512];
    __shared__ float part[8][8][128];
    int row0 = blockIdx.x * 8, jb = blockIdx.y * 128, t = threadIdx.x;
    int w = t >> 5, lane = t & 31;
    {
        float vals[16]; float ss = 0.f;
        #pragma unroll
        for (int i = 0; i < 16; i++) {
            float v = g_ATT[(row0 + w) * 512 + lane + i * 32];
            vals[i] = v; ss += v * v;
        }
        #pragma unroll
        for (int o = 16; o; o >>= 1) ss += __shfl_xor_sync(0xffffffffu, ss, o);
        float rv = rsqrtf(ss * (1.0f / 512.0f) + EPSV);
        #pragma unroll
        for (int i = 0; i < 16; i++) {
            int m = lane + i * 32;
            x_s[w][m] = vals[i] * rv * nw[m];
        }
    }
    __syncthreads();
    int tk = t >> 5, tj = t & 31, j = jb + tj * 4;
    float4 acc[8];
    #pragma unroll
    for (int r = 0; r < 8; r++) acc[r] = make_float4(0.f, 0.f, 0.f, 0.f);
    #pragma unroll 4
    for (int c = tk * 64; c < tk * 64 + 64; c++) {
        float4 w4 = *(const float4*)&w1[(size_t)c * 2048 + j];
        #pragma unroll
        for (int r = 0; r < 8; r++) {
            float x = x_s[r][c];
            acc[r].x += x * w4.x; acc[r].y += x * w4.y;
            acc[r].z += x * w4.z; acc[r].w += x * w4.w;
        }
    }
    #pragma unroll
    for (int r = 0; r < 8; r++) *(float4*)&part[tk][r][tj * 4] = acc[r];
    __syncthreads();
    {
        int r = t >> 5, cq = t & 31, j2 = jb + cq * 4;
        float4 s = make_float4(0.f, 0.f, 0.f, 0.f);
        #pragma unroll
        for (int k2 = 0; k2 < 8; k2++) {
            float4 p = *(const float4*)&part[k2][r][cq * 4];
            s.x += p.x; s.y += p.y; s.z += p.z; s.w += p.w;
        }
        float4 bb = *(const float4*)&b1[j2];
        float4 o;
        o.x = geluf(s.x + bb.x); o.y = geluf(s.y + bb.y);
        o.z = geluf(s.z + bb.z); o.w = geluf(s.w + bb.w);
        *(float4*)&g_H1[(size_t)(row0 + r) * 2048 + j2] = o;
    }
}

// ---------------- K14: ffn2 + residual ----------------------------------------------
__global__ void __launch_bounds__(512) k_ffn2(const float* __restrict__ w2,
                                              const float* __restrict__ b2,
                                              float* __restrict__ out) {
    __shared__ float pool[8192];  // h_s[4][2048] then part[16][4][128]
    int row0 = blockIdx.x * 4, jb = blockIdx.y * 128, t = threadIdx.x;
    for (int idx = t; idx < 8192; idx += 512)
        pool[idx] = g_H1[(size_t)(row0 + (idx >> 11)) * 2048 + (idx & 2047)];
    __syncthreads();
    int tk = t >> 5, tj = t & 31, j = jb + tj * 4;
    float4 acc[4];
    #pragma unroll
    for (int r = 0; r < 4; r++) acc[r] = make_float4(0.f, 0.f, 0.f, 0.f);
    #pragma unroll 4
    for (int c = tk * 128; c < tk * 128 + 128; c++) {
        float4 w4 = *(const float4*)&w2[(size_t)c * 512 + j];
        #pragma unroll
        for (int r = 0; r < 4; r++) {
            float x = pool[r * 2048 + c];
            acc[r].x += x * w4.x; acc[r].y += x * w4.y;
            acc[r].z += x * w4.z; acc[r].w += x * w4.w;
        }
    }
    __syncthreads();
    #pragma unroll
    for (int r = 0; r < 4; r++) *(float4*)&pool[tk * 512 + r * 128 + tj * 4] = acc[r];
    __syncthreads();
    {
        int r = t >> 7, cq = t & 127;
        float s = 0.f;
        #pragma unroll
        for (int k2 = 0; k2 < 16; k2++) s += pool[k2 * 512 + r * 128 + cq];
        int j2 = jb + cq;
        out[(row0 + r) * 512 + j2] = s + b2[j2] + g_ATT[(row0 + r) * 512 + j2];
    }
}

// ---------------- launch -------------------------------------------------------------
extern "C" void kernel_launch(void* const* d_in, const int* in_sizes, int n_in,
                              void* d_out, int out_size) {
    const float* patch   = (const float*)d_in[0];
    const float* mol     = (const float*)d_in[1];
    const float* pe_w1   = (const float*)d_in[2];
    const float* pe_b1   = (const float*)d_in[3];
    const float* pe_w2   = (const float*)d_in[4];
    const float* pe_b2   = (const float*)d_in[5];
    const float* wq      = (const float*)d_in[6];
    const float* bq      = (const float*)d_in[7];
    const float* wkv     = (const float*)d_in[8];
    const float* bkv     = (const float*)d_in[9];
    const float* wproj   = (const float*)d_in[10];
    const float* bproj   = (const float*)d_in[11];
    const float* nmolw   = (const float*)d_in[12];
    const float* npatchw = (const float*)d_in[13];
    const float* ffn_w1  = (const float*)d_in[14];
    const float* ffn_b1  = (const float*)d_in[15];
    const float* ffn_w2  = (const float*)d_in[16];
    const float* ffn_b2  = (const float*)d_in[17];
    const float* ffn_nw  = (const float*)d_in[18];
    float* out = (float*)d_out;
    (void)in_sizes; (void)n_in; (void)out_size;

    k_gel    <<<NN, 256>>>(pe_w1, pe_b1);
    k_peg    <<<dim3(32, 4), 256>>>(pe_w2, pe_b2);
    k_rinv   <<<(BB * NN) / 256, 256>>>(patch);
    k_molq   <<<dim3(16, 4), 256>>>(mol, nmolw, wq, bq);
    k_qbk    <<<4, 256>>>(bkv);
    k_tq2    <<<dim3(8, 2), 256>>>(wkv, npatchw);
    k_qpe2   <<<dim3(32, 8), 256>>>();
    k_scores <<<dim3(32, 8), 256>>>(patch);
    k_softmax<<<BB * 128, 256>>>();
    k_pa     <<<dim3(16, 8), 512>>>(patch);
    k_ppe2   <<<dim3(8, 8), 256>>>();
    k_out    <<<32, 512>>>(wkv, bkv, npatchw);
    k_proj   <<<dim3(16, 4), 256>>>(wproj, bproj);
    k_ffn1   <<<dim3(16, 16), 256>>>(ffn_nw, ffn_w1, ffn_b1);
    k_ffn2   <<<dim3(32, 4), 512>>>(ffn_w2, ffn_b2, out);
}

// round 8
// speedup vs baseline: 4.2282x; 1.1766x over previous
#include <cuda_runtime.h>
#include <mma.h>
#include <math.h>

using namespace nvcuda;

#define BB 8
#define CC 256
#define NN 4096
#define MM 512
#define EE 16
#define NH 8
#define FFNH 2048
#define EPSV 1.1920929e-07f

// ------------- scratch (__device__ globals; no allocation allowed) ---------------
__device__ float g_G   [NN * 256];            // gelu hidden of pos MLP   4 MB
__device__ float g_PE  [NN * MM];             // pos_enc G@W2 (NO bias)   8 MB
__device__ float g_RINV[BB * NN];             // patch rmsnorm rsqrt
__device__ float g_Q   [128 * 512];           // q rows=(b,e)
__device__ float g_MOLN[128 * 512];           // normalized mol (residual)
__device__ float g_TQ  [BB * 128 * 256];      // tq' rows=(b, h*16+e), wp & 0.125 folded
__device__ float g_QBK [BB * NH * EE];        // q . (bk + b2)  (per b,h,e)
__device__ float g_S   [(size_t)BB * 128 * NN];       // scores/probs  16.8 MB
__device__ float g_PAP [(size_t)16 * BB * 128 * 256]; // pa partials   16.8 MB
__device__ float g_OPEP[8 * 8 * 128 * 64];    // p@pe partials
__device__ float g_ATT0[128 * 512];           // attention out (pre-proj)
__device__ float g_ATT [128 * 512];           // attended (post residual)
__device__ float g_H1  [128 * 2048];          // ffn hidden

__device__ __forceinline__ float geluf(float x) {
    return 0.5f * x * (1.0f + erff(x * 0.70710678118654752440f));
}

template <int NWARPS, bool DOMAX>
__device__ __forceinline__ float blk_red(float v, float* red) {
    #pragma unroll
    for (int o = 16; o; o >>= 1) {
        float t = __shfl_xor_sync(0xffffffffu, v, o);
        v = DOMAX ? fmaxf(v, t) : v + t;
    }
    if ((threadIdx.x & 31) == 0) red[threadIdx.x >> 5] = v;
    __syncthreads();
    if (threadIdx.x < 32) {
        float r = (threadIdx.x < NWARPS) ? red[threadIdx.x] : (DOMAX ? -1e30f : 0.0f);
        #pragma unroll
        for (int o = NWARPS >> 1; o; o >>= 1) {
            float t = __shfl_xor_sync(0xffffffffu, r, o);
            r = DOMAX ? fmaxf(r, t) : r + t;
        }
        if (threadIdx.x == 0) red[0] = r;
    }
    __syncthreads();
    float s = red[0];
    __syncthreads();
    return s;
}

// ---------------- K1a: G = gelu(coords @ W1 + b1)  [4096, 256] --------------------
__global__ void k_gel(const float* __restrict__ w1, const float* __restrict__ b1) {
    int n = blockIdx.x, k = threadIdx.x;  // 256
    float cd = (float)(n >> 8)        * 0.0625f;
    float ch = (float)((n >> 4) & 15) * 0.0625f;
    float cw = (float)(n & 15)        * 0.0625f;
    g_G[n * 256 + k] = geluf(cd * w1[k] + ch * w1[256 + k] + cw * w1[512 + k] + b1[k]);
}

// ---------------- K1b: PE = G @ W2 (tf32 TC, NO bias) ------------------------------
// grid(32 m, 4 j), 256 thr (8 warps = 2m x 4n), block tile 128x128, warp 64x32
__global__ void __launch_bounds__(256) k_peg_tc(const float* __restrict__ w2) {
    __shared__ __align__(16) float As[128][36];
    __shared__ __align__(16) float Bs[32][132];
    int m0 = blockIdx.x * 128, j0 = blockIdx.y * 128, t = threadIdx.x;
    int w = t >> 5, wm = w >> 2, wn = w & 3;
    wmma::fragment<wmma::accumulator, 16, 16, 8, float> c[4][2];
    #pragma unroll
    for (int mi = 0; mi < 4; mi++)
        #pragma unroll
        for (int ni = 0; ni < 2; ni++) wmma::fill_fragment(c[mi][ni], 0.0f);
    for (int c0 = 0; c0 < 256; c0 += 32) {
        #pragma unroll
        for (int r = 0; r < 4; r++) {
            int i = t + 256 * r, row = i >> 3, kq = i & 7;
            float4 v = *(const float4*)&g_G[(size_t)(m0 + row) * 256 + c0 + kq * 4];
            As[row][kq * 4 + 0] = wmma::__float_to_tf32(v.x);
            As[row][kq * 4 + 1] = wmma::__float_to_tf32(v.y);
            As[row][kq * 4 + 2] = wmma::__float_to_tf32(v.z);
            As[row][kq * 4 + 3] = wmma::__float_to_tf32(v.w);
        }
        #pragma unroll
        for (int r = 0; r < 4; r++) {
            int i = t + 256 * r, kk = i >> 5, nq = i & 31;
            float4 v = *(const float4*)&w2[(size_t)(c0 + kk) * 512 + j0 + nq * 4];
            Bs[kk][nq * 4 + 0] = wmma::__float_to_tf32(v.x);
            Bs[kk][nq * 4 + 1] = wmma::__float_to_tf32(v.y);
            Bs[kk][nq * 4 + 2] = wmma::__float_to_tf32(v.z);
            Bs[kk][nq * 4 + 3] = wmma::__float_to_tf32(v.w);
        }
        __syncthreads();
        #pragma unroll
        for (int kf = 0; kf < 4; kf++) {
            wmma::fragment<wmma::matrix_a, 16, 16, 8, wmma::precision::tf32, wmma::row_major> af[4];
            wmma::fragment<wmma::matrix_b, 16, 16, 8, wmma::precision::tf32, wmma::row_major> bf[2];
            #pragma unroll
            for (int mi = 0; mi < 4; mi++)
                wmma::load_matrix_sync(af[mi], &As[wm * 64 + mi * 16][kf * 8], 36);
            #pragma unroll
            for (int ni = 0; ni < 2; ni++)
                wmma::load_matrix_sync(bf[ni], &Bs[kf * 8][wn * 32 + ni * 16], 132);
            #pragma unroll
            for (int mi = 0; mi < 4; mi++)
                #pragma unroll
                for (int ni = 0; ni < 2; ni++)
                    wmma::mma_sync(c[mi][ni], af[mi], bf[ni], c[mi][ni]);
        }
        __syncthreads();
    }
    #pragma unroll
    for (int mi = 0; mi < 4; mi++)
        #pragma unroll
        for (int ni = 0; ni < 2; ni++)
            wmma::store_matrix_sync(&g_PE[(size_t)(m0 + wm * 64 + mi * 16) * 512 + j0 + wn * 32 + ni * 16],
                                    c[mi][ni], 512, wmma::mem_row_major);
}

// ---------------- K2: patch rmsnorm rsqrt factor ---------------------------------
__global__ void k_rinv(const float* __restrict__ X) {
    int t = blockIdx.x * blockDim.x + threadIdx.x;
    int b = t >> 12, n = t & (NN - 1);
    const float* p = X + (size_t)b * CC * NN + n;
    float s = 0.0f;
    #pragma unroll 8
    for (int c = 0; c < CC; c++) { float v = p[(size_t)c * NN]; s += v * v; }
    g_RINV[t] = rsqrtf(s * (1.0f / 256.0f) + EPSV);
}

// ---------------- K3: mol rmsnorm + Q projection ----------------------------------
__global__ void __launch_bounds__(256) k_molq(const float* __restrict__ mol,
                                              const float* __restrict__ wmol,
                                              const float* __restrict__ wq,
                                              const float* __restrict__ bq) {
    __shared__ float x_s[8][512];
    __shared__ float part[8][8][128];
    int row0 = blockIdx.x * 8, jb = blockIdx.y * 128;
    int t = threadIdx.x;
    int w = t >> 5, lane = t & 31;
    float vals[16]; float ss = 0.0f;
    #pragma unroll
    for (int i = 0; i < 16; i++) {
        float v = mol[(row0 + w) * 512 + lane + i * 32];
        vals[i] = v; ss += v * v;
    }
    #pragma unroll
    for (int o = 16; o; o >>= 1) ss += __shfl_xor_sync(0xffffffffu, ss, o);
    float rv = rsqrtf(ss * (1.0f / 512.0f) + EPSV);
    #pragma unroll
    for (int i = 0; i < 16; i++) {
        int m = lane + i * 32;
        float xn = vals[i] * rv * wmol[m];
        x_s[w][m] = xn;
        if (blockIdx.y == 0) g_MOLN[(row0 + w) * 512 + m] = xn;
    }
    __syncthreads();
    int tk = w, tj = lane, j = jb + tj * 4;
    float4 acc[8];
    #pragma unroll
    for (int r = 0; r < 8; r++) acc[r] = make_float4(0.f, 0.f, 0.f, 0.f);
    #pragma unroll 4
    for (int c = tk * 64; c < tk * 64 + 64; c++) {
        float4 w4 = *(const float4*)&wq[(size_t)c * 512 + j];
        #pragma unroll
        for (int r = 0; r < 8; r++) {
            float x = x_s[r][c];
            acc[r].x += x * w4.x; acc[r].y += x * w4.y;
            acc[r].z += x * w4.z; acc[r].w += x * w4.w;
        }
    }
    #pragma unroll
    for (int r = 0; r < 8; r++) *(float4*)&part[tk][r][tj * 4] = acc[r];
    __syncthreads();
    {
        int r = t >> 5, cq = t & 31, j2 = jb + cq * 4;
        float4 s = make_float4(0.f, 0.f, 0.f, 0.f);
        #pragma unroll
        for (int k2 = 0; k2 < 8; k2++) {
            float4 p = *(const float4*)&part[k2][r][cq * 4];
            s.x += p.x; s.y += p.y; s.z += p.z; s.w += p.w;
        }
        float4 bv = *(const float4*)&bq[j2];
        s.x += bv.x; s.y += bv.y; s.z += bv.z; s.w += bv.w;
        *(float4*)&g_Q[(row0 + r) * 512 + j2] = s;
    }
}

// ---------------- K4: qbk[b,h,e] = q . (bkv + pe_b2)(h-slice) ----------------------
__global__ void k_qbk(const float* __restrict__ bkv, const float* __restrict__ peb2) {
    int t = blockIdx.x * 256 + threadIdx.x;  // 0..1023
    int b = t >> 7, h = (t >> 4) & 7, e = t & 15;
    float s = 0.f;
    #pragma unroll
    for (int d = 0; d < 64; d++)
        s += g_Q[(b * 16 + e) * 512 + h * 64 + d] * (bkv[h * 64 + d] + peb2[h * 64 + d]);
    g_QBK[(b * 8 + h) * 16 + e] = s;
}

// ---------------- K5: tq'[b,h,e,c] = 0.125*wp[c]*(q_h . Wk_h[c,:]) -----------------
__global__ void __launch_bounds__(256) k_tq2(const float* __restrict__ wkv,
                                             const float* __restrict__ wp) {
    __shared__ float As[16][128];
    __shared__ float Bs[16][128];
    int h = blockIdx.x, c0b = blockIdx.y * 128, t = threadIdx.x;
    int tr = t >> 4, tc = t & 15;
    float acc[8][8];
    #pragma unroll
    for (int i = 0; i < 8; i++)
        #pragma unroll
        for (int j = 0; j < 8; j++) acc[i][j] = 0.f;
    for (int k0 = 0; k0 < 64; k0 += 16) {
        {
            int r = t >> 1, k8 = (t & 1) * 8;
            int b = r >> 4, e = r & 15;
            const float* src = &g_Q[(b * 16 + e) * 512 + h * 64 + k0 + k8];
            float4 a0 = *(const float4*)&src[0];
            float4 a1 = *(const float4*)&src[4];
            As[k8 + 0][r] = a0.x; As[k8 + 1][r] = a0.y; As[k8 + 2][r] = a0.z; As[k8 + 3][r] = a0.w;
            As[k8 + 4][r] = a1.x; As[k8 + 5][r] = a1.y; As[k8 + 6][r] = a1.z; As[k8 + 7][r] = a1.w;
        }
        {
            int c = t >> 1, k8 = (t & 1) * 8;
            const float* src = &wkv[(size_t)(c0b + c) * 1024 + h * 64 + k0 + k8];
            float4 v0 = *(const float4*)&src[0];
            float4 v1 = *(const float4*)&src[4];
            Bs[k8 + 0][c] = v0.x; Bs[k8 + 1][c] = v0.y; Bs[k8 + 2][c] = v0.z; Bs[k8 + 3][c] = v0.w;
            Bs[k8 + 4][c] = v1.x; Bs[k8 + 5][c] = v1.y; Bs[k8 + 6][c] = v1.z; Bs[k8 + 7][c] = v1.w;
        }
        __syncthreads();
        #pragma unroll
        for (int kk = 0; kk < 16; kk++) {
            float4 a0 = *(const float4*)&As[kk][tr * 8];
            float4 a1 = *(const float4*)&As[kk][tr * 8 + 4];
            float4 b0 = *(const float4*)&Bs[kk][tc * 8];
            float4 b1 = *(const float4*)&Bs[kk][tc * 8 + 4];
            float a[8] = {a0.x, a0.y, a0.z, a0.w, a1.x, a1.y, a1.z, a1.w};
            float bb[8] = {b0.x, b0.y, b0.z, b0.w, b1.x, b1.y, b1.z, b1.w};
            #pragma unroll
            for (int i = 0; i < 8; i++)
                #pragma unroll
                for (int j = 0; j < 8; j++) acc[i][j] += a[i] * bb[j];
        }
        __syncthreads();
    }
    float4 wp0 = *(const float4*)&wp[c0b + tc * 8];
    float4 wp1 = *(const float4*)&wp[c0b + tc * 8 + 4];
    float wpv[8] = {wp0.x, wp0.y, wp0.z, wp0.w, wp1.x, wp1.y, wp1.z, wp1.w};
    #pragma unroll
    for (int i = 0; i < 8; i++) {
        int r = tr * 8 + i, b = r >> 4, e = r & 15;
        float* dst = &g_TQ[(size_t)(b * 128 + h * 16 + e) * 256 + c0b + tc * 8];
        #pragma unroll
        for (int j = 0; j < 8; j++) dst[j] = acc[i][j] * wpv[j] * 0.125f;
    }
}

// ---------------- K6: S = 0.125*(q_h @ PE_h^T + qbk)  (per h GEMM) -----------------
__global__ void __launch_bounds__(256) k_qpe2() {
    __shared__ float As[16][128];
    __shared__ float Bs[16][128];
    int n0 = blockIdx.x * 128, h = blockIdx.y, t = threadIdx.x;
    int tr = t >> 4, tc = t & 15;
    float acc[8][8];
    #pragma unroll
    for (int i = 0; i < 8; i++)
        #pragma unroll
        for (int j = 0; j < 8; j++) acc[i][j] = 0.f;
    for (int k0 = 0; k0 < 64; k0 += 16) {
        {
            int r = t >> 1, k8 = (t & 1) * 8;
            int b = r >> 4, e = r & 15;
            const float* src = &g_Q[(b * 16 + e) * 512 + h * 64 + k0 + k8];
            float4 a0 = *(const float4*)&src[0];
            float4 a1 = *(const float4*)&src[4];
            As[k8 + 0][r] = a0.x; As[k8 + 1][r] = a0.y; As[k8 + 2][r] = a0.z; As[k8 + 3][r] = a0.w;
            As[k8 + 4][r] = a1.x; As[k8 + 5][r] = a1.y; As[k8 + 6][r] = a1.z; As[k8 + 7][r] = a1.w;
        }
        {
            int nl = t >> 1, k8 = (t & 1) * 8;
            const float* src = &g_PE[(size_t)(n0 + nl) * 512 + h * 64 + k0 + k8];
            float4 v0 = *(const float4*)&src[0];
            float4 v1 = *(const float4*)&src[4];
            Bs[k8 + 0][nl] = v0.x; Bs[k8 + 1][nl] = v0.y; Bs[k8 + 2][nl] = v0.z; Bs[k8 + 3][nl] = v0.w;
            Bs[k8 + 4][nl] = v1.x; Bs[k8 + 5][nl] = v1.y; Bs[k8 + 6][nl] = v1.z; Bs[k8 + 7][nl] = v1.w;
        }
        __syncthreads();
        #pragma unroll
        for (int kk = 0; kk < 16; kk++) {
            float4 a0 = *(const float4*)&As[kk][tr * 8];
            float4 a1 = *(const float4*)&As[kk][tr * 8 + 4];
            float4 b0 = *(const float4*)&Bs[kk][tc * 8];
            float4 b1 = *(const float4*)&Bs[kk][tc * 8 + 4];
            float a[8] = {a0.x, a0.y, a0.z, a0.w, a1.x, a1.y, a1.z, a1.w};
            float bb[8] = {b0.x, b0.y, b0.z, b0.w, b1.x, b1.y, b1.z, b1.w};
            #pragma unroll
            for (int i = 0; i < 8; i++)
                #pragma unroll
                for (int j = 0; j < 8; j++) acc[i][j] += a[i] * bb[j];
        }
        __syncthreads();
    }
    #pragma unroll
    for (int i = 0; i < 8; i++) {
        int r = tr * 8 + i, b = r >> 4, e = r & 15;
        float qb = g_QBK[(b * 8 + h) * 16 + e];
        float* dst = &g_S[(size_t)((b * 8 + h) * 16 + e) * 4096 + n0 + tc * 8];
        *(float4*)&dst[0] = make_float4((acc[i][0] + qb) * 0.125f, (acc[i][1] + qb) * 0.125f,
                                        (acc[i][2] + qb) * 0.125f, (acc[i][3] + qb) * 0.125f);
        *(float4*)&dst[4] = make_float4((acc[i][4] + qb) * 0.125f, (acc[i][5] + qb) * 0.125f,
                                        (acc[i][6] + qb) * 0.125f, (acc[i][7] + qb) * 0.125f);
    }
}

// ---------------- K7: scores (tf32 TC): S += tq'(0.125 folded) @ (X*rinv) ----------
// grid(32 nt, 8 b), 256 thr (2m x 4n warps), tile 128x128, K=256
__global__ void __launch_bounds__(256) k_scores_tc(const float* __restrict__ X) {
    __shared__ __align__(16) float As[128][36];
    __shared__ __align__(16) float Bs[32][132];
    __shared__ __align__(16) float rs[128];
    int n0 = blockIdx.x * 128, b = blockIdx.y, t = threadIdx.x;
    int w = t >> 5, wm = w >> 2, wn = w & 3;
    const float* Xb = X + (size_t)b * CC * NN;
    const float* TQ = g_TQ + (size_t)b * 128 * 256;
    float* Sb = g_S + (size_t)b * 128 * 4096;
    if (t < 32) *(float4*)&rs[t * 4] = *(const float4*)&g_RINV[b * 4096 + n0 + t * 4];
    __syncthreads();
    wmma::fragment<wmma::accumulator, 16, 16, 8, float> c[4][2];
    #pragma unroll
    for (int mi = 0; mi < 4; mi++)
        #pragma unroll
        for (int ni = 0; ni < 2; ni++)
            wmma::load_matrix_sync(c[mi][ni],
                &Sb[(size_t)(wm * 64 + mi * 16) * 4096 + n0 + wn * 32 + ni * 16],
                4096, wmma::mem_row_major);
    for (int c0 = 0; c0 < 256; c0 += 32) {
        #pragma unroll
        for (int r = 0; r < 4; r++) {
            int i = t + 256 * r, row = i >> 3, kq = i & 7;
            float4 v = *(const float4*)&TQ[(size_t)row * 256 + c0 + kq * 4];
            As[row][kq * 4 + 0] = wmma::__float_to_tf32(v.x);
            As[row][kq * 4 + 1] = wmma::__float_to_tf32(v.y);
            As[row][kq * 4 + 2] = wmma::__float_to_tf32(v.z);
            As[row][kq * 4 + 3] = wmma::__float_to_tf32(v.w);
        }
        #pragma unroll
        for (int r = 0; r < 4; r++) {
            int i = t + 256 * r, kk = i >> 5, nq = i & 31;
            float4 v = *(const float4*)&Xb[(size_t)(c0 + kk) * 4096 + n0 + nq * 4];
            Bs[kk][nq * 4 + 0] = wmma::__float_to_tf32(v.x * rs[nq * 4 + 0]);
            Bs[kk][nq * 4 + 1] = wmma::__float_to_tf32(v.y * rs[nq * 4 + 1]);
            Bs[kk][nq * 4 + 2] = wmma::__float_to_tf32(v.z * rs[nq * 4 + 2]);
            Bs[kk][nq * 4 + 3] = wmma::__float_to_tf32(v.w * rs[nq * 4 + 3]);
        }
        __syncthreads();
        #pragma unroll
        for (int kf = 0; kf < 4; kf++) {
            wmma::fragment<wmma::matrix_a, 16, 16, 8, wmma::precision::tf32, wmma::row_major> af[4];
            wmma::fragment<wmma::matrix_b, 16, 16, 8, wmma::precision::tf32, wmma::row_major> bf[2];
            #pragma unroll
            for (int mi = 0; mi < 4; mi++)
                wmma::load_matrix_sync(af[mi], &As[wm * 64 + mi * 16][kf * 8], 36);
            #pragma unroll
            for (int ni = 0; ni < 2; ni++)
                wmma::load_matrix_sync(bf[ni], &Bs[kf * 8][wn * 32 + ni * 16], 132);
            #pragma unroll
            for (int mi = 0; mi < 4; mi++)
                #pragma unroll
                for (int ni = 0; ni < 2; ni++)
                    wmma::mma_sync(c[mi][ni], af[mi], bf[ni], c[mi][ni]);
        }
        __syncthreads();
    }
    #pragma unroll
    for (int mi = 0; mi < 4; mi++)
        #pragma unroll
        for (int ni = 0; ni < 2; ni++)
            wmma::store_matrix_sync(&Sb[(size_t)(wm * 64 + mi * 16) * 4096 + n0 + wn * 32 + ni * 16],
                                    c[mi][ni], 4096, wmma::mem_row_major);
}

// ---------------- K8: softmax over n=4096 ------------------------------------------
__global__ void k_softmax() {
    __shared__ float red[32];
    int row = blockIdx.x;
    float* s = g_S + (size_t)row * NN;
    int t = threadIdx.x;  // 256
    float loc[16];
    float m = -1e30f;
    #pragma unroll
    for (int i = 0; i < 16; i++) { loc[i] = s[t + i * 256]; m = fmaxf(m, loc[i]); }
    m = blk_red<8, true>(m, red);
    float sum = 0.0f;
    #pragma unroll
    for (int i = 0; i < 16; i++) { loc[i] = expf(loc[i] - m); sum += loc[i]; }
    sum = blk_red<8, false>(sum, red);
    float inv = 1.0f / sum;
    #pragma unroll
    for (int i = 0; i < 16; i++) s[t + i * 256] = loc[i] * inv;
}

// ---------------- K9: pa partials (tf32 TC): (p*rinv) @ X^T ------------------------
// grid(16 ks, 8 b), 512 thr (2m x 8n warps), tile 128x256, Kchunk=256 (inner 16)
__global__ void __launch_bounds__(512) k_pa_tc(const float* __restrict__ X) {
    __shared__ __align__(16) float As[128][20];
    __shared__ __align__(16) float Bs[256][20];
    int ks = blockIdx.x, b = blockIdx.y, t = threadIdx.x;
    int nbase = ks * 256;
    int w = t >> 5, wm = w >> 3, wn = w & 7;
    const float* Xb = X + (size_t)b * CC * NN;
    wmma::fragment<wmma::accumulator, 16, 16, 8, float> c[4][2];
    #pragma unroll
    for (int mi = 0; mi < 4; mi++)
        #pragma unroll
        for (int ni = 0; ni < 2; ni++) wmma::fill_fragment(c[mi][ni], 0.0f);
    for (int k0 = 0; k0 < 256; k0 += 16) {
        {
            int row = t >> 2, kq = t & 3;
            int n = nbase + k0 + kq * 4;
            float4 p  = *(const float4*)&g_S[(size_t)(b * 128 + row) * 4096 + n];
            float4 rv = *(const float4*)&g_RINV[b * 4096 + n];
            As[row][kq * 4 + 0] = wmma::__float_to_tf32(p.x * rv.x);
            As[row][kq * 4 + 1] = wmma::__float_to_tf32(p.y * rv.y);
            As[row][kq * 4 + 2] = wmma::__float_to_tf32(p.z * rv.z);
            As[row][kq * 4 + 3] = wmma::__float_to_tf32(p.w * rv.w);
        }
        #pragma unroll
        for (int r = 0; r < 2; r++) {
            int i = t + 512 * r, cc = i >> 2, kq = i & 3;
            float4 v = *(const float4*)&Xb[(size_t)cc * 4096 + nbase + k0 + kq * 4];
            Bs[cc][kq * 4 + 0] = wmma::__float_to_tf32(v.x);
            Bs[cc][kq * 4 + 1] = wmma::__float_to_tf32(v.y);
            Bs[cc][kq * 4 + 2] = wmma::__float_to_tf32(v.z);
            Bs[cc][kq * 4 + 3] = wmma::__float_to_tf32(v.w);
        }
        __syncthreads();
        #pragma unroll
        for (int kf = 0; kf < 2; kf++) {
            wmma::fragment<wmma::matrix_a, 16, 16, 8, wmma::precision::tf32, wmma::row_major> af[4];
            wmma::fragment<wmma::matrix_b, 16, 16, 8, wmma::precision::tf32, wmma::col_major> bf[2];
            #pragma unroll
            for (int mi = 0; mi < 4; mi++)
                wmma::load_matrix_sync(af[mi], &As[wm * 64 + mi * 16][kf * 8], 20);
            #pragma unroll
            for (int ni = 0; ni < 2; ni++)
                wmma::load_matrix_sync(bf[ni], &Bs[wn * 32 + ni * 16][kf * 8], 20);
            #pragma unroll
            for (int mi = 0; mi < 4; mi++)
                #pragma unroll
                for (int ni = 0; ni < 2; ni++)
                    wmma::mma_sync(c[mi][ni], af[mi], bf[ni], c[mi][ni]);
        }
        __syncthreads();
    }
    #pragma unroll
    for (int mi = 0; mi < 4; mi++)
        #pragma unroll
        for (int ni = 0; ni < 2; ni++)
            wmma::store_matrix_sync(
                &g_PAP[(size_t)((ks * 8 + b) * 128 + wm * 64 + mi * 16) * 256 + wn * 32 + ni * 16],
                c[mi][ni], 256, wmma::mem_row_major);
}

// ---------------- K10: ope partials: p @ PE_h  (per-h GEMM, K=4096 split 8) --------
__global__ void __launch_bounds__(256) k_ppe2() {
    __shared__ float As[16][128];
    __shared__ float Bs[16][64];
    int h = blockIdx.x, ks = blockIdx.y, t = threadIdx.x;
    int nb = ks * 512;
    int tr = t >> 4, tc = t & 15;
    float acc[8][4];
    #pragma unroll
    for (int i = 0; i < 8; i++)
        #pragma unroll
        for (int j = 0; j < 4; j++) acc[i][j] = 0.f;
    for (int k0 = 0; k0 < 512; k0 += 16) {
        {
            int r = t >> 1, k8 = (t & 1) * 8;
            int b = r >> 4, e = r & 15;
            const float* src = &g_S[(size_t)((b * 8 + h) * 16 + e) * 4096 + nb + k0 + k8];
            float4 v0 = *(const float4*)&src[0];
            float4 v1 = *(const float4*)&src[4];
            As[k8 + 0][r] = v0.x; As[k8 + 1][r] = v0.y; As[k8 + 2][r] = v0.z; As[k8 + 3][r] = v0.w;
            As[k8 + 4][r] = v1.x; As[k8 + 5][r] = v1.y; As[k8 + 6][r] = v1.z; As[k8 + 7][r] = v1.w;
        }
        {
            int kk = t >> 4, d4 = (t & 15) * 4;
            *(float4*)&Bs[kk][d4] = *(const float4*)&g_PE[(size_t)(nb + k0 + kk) * 512 + h * 64 + d4];
        }
        __syncthreads();
        #pragma unroll
        for (int kk = 0; kk < 16; kk++) {
            float4 a0 = *(const float4*)&As[kk][tr * 8];
            float4 a1 = *(const float4*)&As[kk][tr * 8 + 4];
            float4 b4 = *(const float4*)&Bs[kk][tc * 4];
            float a[8] = {a0.x, a0.y, a0.z, a0.w, a1.x, a1.y, a1.z, a1.w};
            float bb[4] = {b4.x, b4.y, b4.z, b4.w};
            #pragma unroll
            for (int i = 0; i < 8; i++)
                #pragma unroll
                for (int j = 0; j < 4; j++) acc[i][j] += a[i] * bb[j];
        }
        __syncthreads();
    }
    #pragma unroll
    for (int i = 0; i < 8; i++) {
        int r = tr * 8 + i;
        float* dst = &g_OPEP[(size_t)((ks * 8 + h) * 128 + r) * 64 + tc * 4];
        *(float4*)dst = make_float4(acc[i][0], acc[i][1], acc[i][2], acc[i][3]);
    }
}

// ---------------- K11: out0 = (pa*wp-reduced) @ Wv + ope + bv + b2 -----------------
__global__ void __launch_bounds__(512) k_out(const float* __restrict__ wkv,
                                             const float* __restrict__ bkv,
                                             const float* __restrict__ peb2,
                                             const float* __restrict__ wp) {
    __shared__ float pool[8192];
    __shared__ float ope_s[4][512];
    int row0 = blockIdx.x * 4;
    int t = threadIdx.x;
    for (int idx = t; idx < 8192; idx += 512) {
        int r = idx >> 11, rest = idx & 2047, h = rest >> 8, c = rest & 255;
        int row = row0 + r, b = row >> 4, e = row & 15;
        float s = 0.f;
        #pragma unroll
        for (int ks = 0; ks < 16; ks++)
            s += g_PAP[(size_t)((ks * 8 + b) * 128 + h * 16 + e) * 256 + c];
        pool[idx] = s * wp[c];
    }
    for (int idx = t; idx < 2048; idx += 512) {
        int r = idx >> 9, j = idx & 511;
        int row = row0 + r, b = row >> 4, e = row & 15;
        int h = j >> 6, d = j & 63;
        float s = 0.f;
        #pragma unroll
        for (int ks = 0; ks < 8; ks++)
            s += g_OPEP[(size_t)((ks * 8 + h) * 128 + b * 16 + e) * 64 + d];
        ope_s[r][j] = s;
    }
    __syncthreads();
    int tj = t & 127, tk = t >> 7;
    int h = tj >> 4;
    float4 acc[4];
    #pragma unroll
    for (int r = 0; r < 4; r++) acc[r] = make_float4(0.f, 0.f, 0.f, 0.f);
    #pragma unroll 4
    for (int c = tk * 64; c < tk * 64 + 64; c++) {
        float4 w4 = *(const float4*)&wkv[(size_t)c * 1024 + 512 + tj * 4];
        #pragma unroll
        for (int r = 0; r < 4; r++) {
            float p = pool[r * 2048 + h * 256 + c];
            acc[r].x += p * w4.x; acc[r].y += p * w4.y;
            acc[r].z += p * w4.z; acc[r].w += p * w4.w;
        }
    }
    __syncthreads();
    #pragma unroll
    for (int r = 0; r < 4; r++) *(float4*)&pool[(tk * 4 + r) * 512 + tj * 4] = acc[r];
    __syncthreads();
    {
        int r = t >> 7, j0 = (t & 127) * 4;
        float4 s = make_float4(0.f, 0.f, 0.f, 0.f);
        #pragma unroll
        for (int k2 = 0; k2 < 4; k2++) {
            float4 p = *(const float4*)&pool[(k2 * 4 + r) * 512 + j0];
            s.x += p.x; s.y += p.y; s.z += p.z; s.w += p.w;
        }
        float4 bv = *(const float4*)&bkv[512 + j0];
        float4 b2 = *(const float4*)&peb2[j0];
        float4 op = *(const float4*)&ope_s[r][j0];
        s.x += bv.x + b2.x + op.x; s.y += bv.y + b2.y + op.y;
        s.z += bv.z + b2.z + op.z; s.w += bv.w + b2.w + op.w;
        *(float4*)&g_ATT0[(row0 + r) * 512 + j0] = s;
    }
}

// ---------------- K12: proj + residual ---------------------------------------------
__global__ void __launch_bounds__(256) k_proj(const float* __restrict__ wproj,
                                              const float* __restrict__ bproj) {
    __shared__ float x_s[8][512];
    __shared__ float part[8][8][128];
    int row0 = blockIdx.x * 8, jb = blockIdx.y * 128, t = threadIdx.x;
    for (int idx = t; idx < 4096; idx += 256)
        x_s[idx >> 9][idx & 511] = g_ATT0[(row0 + (idx >> 9)) * 512 + (idx & 511)];
    __syncthreads();
    int tk = t >> 5, tj = t & 31, j = jb + tj * 4;
    float4 acc[8];
    #pragma unroll
    for (int r = 0; r < 8; r++) acc[r] = make_float4(0.f, 0.f, 0.f, 0.f);
    #pragma unroll 4
    for (int c = tk * 64; c < tk * 64 + 64; c++) {
        float4 w4 = *(const float4*)&wproj[(size_t)c * 512 + j];
        #pragma unroll
        for (int r = 0; r < 8; r++) {
            float x = x_s[r][c];
            acc[r].x += x * w4.x; acc[r].y += x * w4.y;
            acc[r].z += x * w4.z; acc[r].w += x * w4.w;
        }
    }
    #pragma unroll
    for (int r = 0; r < 8; r++) *(float4*)&part[tk][r][tj * 4] = acc[r];
    __syncthreads();
    {
        int r = t >> 5, cq = t & 31, j2 = jb + cq * 4;
        float4 s = make_float4(0.f, 0.f, 0.f, 0.f);
        #pragma unroll
        for (int k2 = 0; k2 < 8; k2++) {
            float4 p = *(const float4*)&part[k2][r][cq * 4];
            s.x += p.x; s.y += p.y; s.z += p.z; s.w += p.w;
        }
        float4 bp = *(const float4*)&bproj[j2];
        float4 mn = *(const float4*)&g_MOLN[(row0 + r) * 512 + j2];
        s.x += bp.x + mn.x; s.y += bp.y + mn.y;
        s.z += bp.z + mn.z; s.w += bp.w + mn.w;
        *(float4*)&g_ATT[(row0 + r) * 512 + j2] = s;
    }
}

// ---------------- K13: ffn1 (fused rmsnorm) + gelu ----------------------------------
__global__ void __launch_bounds__(256) k_ffn1(const float* __restrict__ nw,
                                              const float* __restrict__ w1,
                                              const float* __restrict__ b1) {
    __shared__ float x_s[8][512];
    __shared__ float part[8][8][128];
    int row0 = blockIdx.x * 8, jb = blockIdx.y * 128, t = threadIdx.x;
    int w = t >> 5, lane = t & 31;
    {
        float vals[16]; float ss = 0.f;
        #pragma unroll
        for (int i = 0; i < 16; i++) {
            float v = g_ATT[(row0 + w) * 512 + lane + i * 32];
            vals[i] = v; ss += v * v;
        }
        #pragma unroll
        for (int o = 16; o; o >>= 1) ss += __shfl_xor_sync(0xffffffffu, ss, o);
        float rv = rsqrtf(ss * (1.0f / 512.0f) + EPSV);
        #pragma unroll
        for (int i = 0; i < 16; i++) {
            int m = lane + i * 32;
            x_s[w][m] = vals[i] * rv * nw[m];
        }
    }
    __syncthreads();
    int tk = t >> 5, tj = t & 31, j = jb + tj * 4;
    float4 acc[8];
    #pragma unroll
    for (int r = 0; r < 8; r++) acc[r] = make_float4(0.f, 0.f, 0.f, 0.f);
    #pragma unroll 4
    for (int c = tk * 64; c < tk * 64 + 64; c++) {
        float4 w4 = *(const float4*)&w1[(size_t)c * 2048 + j];
        #pragma unroll
        for (int r = 0; r < 8; r++) {
            float x = x_s[r][c];
            acc[r].x += x * w4.x; acc[r].y += x * w4.y;
            acc[r].z += x * w4.z; acc[r].w += x * w4.w;
        }
    }
    #pragma unroll
    for (int r = 0; r < 8; r++) *(float4*)&part[tk][r][tj * 4] = acc[r];
    __syncthreads();
    {
        int r = t >> 5, cq = t & 31, j2 = jb + cq * 4;
        float4 s = make_float4(0.f, 0.f, 0.f, 0.f);
        #pragma unroll
        for (int k2 = 0; k2 < 8; k2++) {
            float4 p = *(const float4*)&part[k2][r][cq * 4];
            s.x += p.x; s.y += p.y; s.z += p.z; s.w += p.w;
        }
        float4 bb = *(const float4*)&b1[j2];
        float4 o;
        o.x = geluf(s.x + bb.x); o.y = geluf(s.y + bb.y);
        o.z = geluf(s.z + bb.z); o.w = geluf(s.w + bb.w);
        *(float4*)&g_H1[(size_t)(row0 + r) * 2048 + j2] = o;
    }
}

// ---------------- K14: ffn2 + residual ----------------------------------------------
__global__ void __launch_bounds__(512) k_ffn2(const float* __restrict__ w2,
                                              const float* __restrict__ b2,
                                              float* __restrict__ out) {
    __shared__ float pool[8192];
    int row0 = blockIdx.x * 4, jb = blockIdx.y * 128, t = threadIdx.x;
    for (int idx = t; idx < 8192; idx += 512)
        pool[idx] = g_H1[(size_t)(row0 + (idx >> 11)) * 2048 + (idx & 2047)];
    __syncthreads();
    int tk = t >> 5, tj = t & 31, j = jb + tj * 4;
    float4 acc[4];
    #pragma unroll
    for (int r = 0; r < 4; r++) acc[r] = make_float4(0.f, 0.f, 0.f, 0.f);
    #pragma unroll 4
    for (int c = tk * 128; c < tk * 128 + 128; c++) {
        float4 w4 = *(const float4*)&w2[(size_t)c * 512 + j];
        #pragma unroll
        for (int r = 0; r < 4; r++) {
            float x = pool[r * 2048 + c];
            acc[r].x += x * w4.x; acc[r].y += x * w4.y;
            acc[r].z += x * w4.z; acc[r].w += x * w4.w;
        }
    }
    __syncthreads();
    #pragma unroll
    for (int r = 0; r < 4; r++) *(float4*)&pool[tk * 512 + r * 128 + tj * 4] = acc[r];
    __syncthreads();
    {
        int r = t >> 7, cq = t & 127;
        float s = 0.f;
        #pragma unroll
        for (int k2 = 0; k2 < 16; k2++) s += pool[k2 * 512 + r * 128 + cq];
        int j2 = jb + cq;
        out[(row0 + r) * 512 + j2] = s + b2[j2] + g_ATT[(row0 + r) * 512 + j2];
    }
}

// ---------------- launch -------------------------------------------------------------
extern "C" void kernel_launch(void* const* d_in, const int* in_sizes, int n_in,
                              void* d_out, int out_size) {
    const float* patch   = (const float*)d_in[0];
    const float* mol     = (const float*)d_in[1];
    const float* pe_w1   = (const float*)d_in[2];
    const float* pe_b1   = (const float*)d_in[3];
    const float* pe_w2   = (const float*)d_in[4];
    const float* pe_b2   = (const float*)d_in[5];
    const float* wq      = (const float*)d_in[6];
    const float* bq      = (const float*)d_in[7];
    const float* wkv     = (const float*)d_in[8];
    const float* bkv     = (const float*)d_in[9];
    const float* wproj   = (const float*)d_in[10];
    const float* bproj   = (const float*)d_in[11];
    const float* nmolw   = (const float*)d_in[12];
    const float* npatchw = (const float*)d_in[13];
    const float* ffn_w1  = (const float*)d_in[14];
    const float* ffn_b1  = (const float*)d_in[15];
    const float* ffn_w2  = (const float*)d_in[16];
    const float* ffn_b2  = (const float*)d_in[17];
    const float* ffn_nw  = (const float*)d_in[18];
    float* out = (float*)d_out;
    (void)in_sizes; (void)n_in; (void)out_size;

    k_gel      <<<NN, 256>>>(pe_w1, pe_b1);
    k_peg_tc   <<<dim3(32, 4), 256>>>(pe_w2);
    k_rinv     <<<(BB * NN) / 256, 256>>>(patch);
    k_molq     <<<dim3(16, 4), 256>>>(mol, nmolw, wq, bq);
    k_qbk      <<<4, 256>>>(bkv, pe_b2);
    k_tq2      <<<dim3(8, 2), 256>>>(wkv, npatchw);
    k_qpe2     <<<dim3(32, 8), 256>>>();
    k_scores_tc<<<dim3(32, 8), 256>>>(patch);
    k_softmax  <<<BB * 128, 256>>>();
    k_pa_tc    <<<dim3(16, 8), 512>>>(patch);
    k_ppe2     <<<dim3(8, 8), 256>>>();
    k_out      <<<32, 512>>>(wkv, bkv, pe_b2, npatchw);
    k_proj     <<<dim3(16, 4), 256>>>(wproj, bproj);
    k_ffn1     <<<dim3(16, 16), 256>>>(ffn_nw, ffn_w1, ffn_b1);
    k_ffn2     <<<dim3(32, 4), 512>>>(ffn_w2, ffn_b2, out);
}